// round 1
// baseline (speedup 1.0000x reference)
#include <cuda_runtime.h>
#include <math.h>

// ---------------------------------------------------------------------------
// Problem constants
// ---------------------------------------------------------------------------
#define B_   4
#define T_   2048
#define C_   1024
#define H_   16
#define D_   64
#define M_   (B_ * T_)        // 8192 rows
#define N_QKV (3 * C_)        // 3072
#define SCALE 0.125f          // 1/sqrt(64)

// Scratch (allocation-free rule: __device__ globals)
__device__ float g_qkv[M_ * N_QKV];   // [8192, 3072]
__device__ float g_att[M_ * C_];      // [8192, 1024]  (pre-projection attn out)

// ---------------------------------------------------------------------------
// GEMM: C[m,n] = sum_k A[m,k] * W[n,k] + bias[n]
// A: [M,K] row-major, W: [N,K] row-major (i.e. computes A @ W^T + b)
// Tiles: 128x128x16, 256 threads, 8x8 per thread.
// ---------------------------------------------------------------------------
__global__ __launch_bounds__(256)
void gemm_bias_kernel(const float* __restrict__ A,
                      const float* __restrict__ W,
                      const float* __restrict__ bias,
                      float* __restrict__ C,
                      int M, int N, int K)
{
    __shared__ float As[16][132];   // [k][m], pad 4 -> 2-way max on stores
    __shared__ float Bs[16][132];   // [k][n]

    const int tid = threadIdx.x;
    const int tx  = tid & 15;       // 0..15
    const int ty  = tid >> 4;       // 0..15
    const int bm  = blockIdx.y * 128;
    const int bn  = blockIdx.x * 128;

    float acc[8][8];
#pragma unroll
    for (int i = 0; i < 8; i++)
#pragma unroll
        for (int j = 0; j < 8; j++) acc[i][j] = 0.0f;

    for (int k0 = 0; k0 < K; k0 += 16) {
        // Load 128x16 tiles of A and W, transposed into smem.
        // 512 float4 per tile, 2 per thread.
#pragma unroll
        for (int i = 0; i < 2; i++) {
            int idx = tid + i * 256;
            int r   = idx >> 2;        // 0..127
            int c4  = idx & 3;         // 0..3
            float4 a = *(const float4*)(A + (size_t)(bm + r) * K + k0 + c4 * 4);
            As[c4 * 4 + 0][r] = a.x;
            As[c4 * 4 + 1][r] = a.y;
            As[c4 * 4 + 2][r] = a.z;
            As[c4 * 4 + 3][r] = a.w;
            float4 b = *(const float4*)(W + (size_t)(bn + r) * K + k0 + c4 * 4);
            Bs[c4 * 4 + 0][r] = b.x;
            Bs[c4 * 4 + 1][r] = b.y;
            Bs[c4 * 4 + 2][r] = b.z;
            Bs[c4 * 4 + 3][r] = b.w;
        }
        __syncthreads();

#pragma unroll
        for (int k = 0; k < 16; k++) {
            float a[8], b[8];
            // A rows: ty*8 + i (contiguous) -> float4 broadcast loads
            float4 a0 = *(const float4*)&As[k][ty * 8];
            float4 a1 = *(const float4*)&As[k][ty * 8 + 4];
            a[0] = a0.x; a[1] = a0.y; a[2] = a0.z; a[3] = a0.w;
            a[4] = a1.x; a[5] = a1.y; a[6] = a1.z; a[7] = a1.w;
            // B cols strided: tx + 16*j (conflict-free scalar)
#pragma unroll
            for (int j = 0; j < 8; j++) b[j] = Bs[k][tx + 16 * j];
#pragma unroll
            for (int i = 0; i < 8; i++)
#pragma unroll
                for (int j = 0; j < 8; j++)
                    acc[i][j] = fmaf(a[i], b[j], acc[i][j]);
        }
        __syncthreads();
    }

    // Epilogue: bias + store
    float bv[8];
#pragma unroll
    for (int j = 0; j < 8; j++) bv[j] = bias[bn + tx + 16 * j];
#pragma unroll
    for (int i = 0; i < 8; i++) {
        size_t row = (size_t)(bm + ty * 8 + i);
#pragma unroll
        for (int j = 0; j < 8; j++)
            C[row * N + bn + tx + 16 * j] = acc[i][j] + bv[j];
    }
}

// ---------------------------------------------------------------------------
// Flash attention (fp32, causal). One block = 64 queries of one (b,h).
// Reads q/k/v in place from g_qkv with strides; writes g_att in [B,T,H*D].
// smem: Qs[64][68], Ks[64][68], Ss[64][68], Vs[64][64], c_s[64], l_s[64]
// Thread map (16x16): S/O element (row = ty+16i, col = tx+16j).
// Softmax row groups: row = tid/4, 16 cols per lane.
// ---------------------------------------------------------------------------
#define QS_STRIDE 68
#define FL_SMEM_FLOATS (3 * 64 * QS_STRIDE + 64 * 64 + 128)

__global__ __launch_bounds__(256)
void flash_kernel(const float* __restrict__ qkv, float* __restrict__ out)
{
    extern __shared__ float sm[];
    float* Qs  = sm;                        // [64][68]
    float* Ks  = Qs + 64 * QS_STRIDE;       // [64][68]
    float* Ss  = Ks + 64 * QS_STRIDE;       // [64][68]
    float* Vs  = Ss + 64 * QS_STRIDE;       // [64][64]
    float* c_s = Vs + 64 * 64;              // [64]
    float* l_s = c_s + 64;                  // [64]

    const int qt  = (int)gridDim.x - 1 - (int)blockIdx.x;  // heavy tiles first
    const int bh  = blockIdx.y;
    const int b   = bh >> 4;
    const int h   = bh & 15;
    const int tid = threadIdx.x;
    const int tx  = tid & 15;
    const int ty  = tid >> 4;
    const int srow  = tid >> 2;   // softmax row 0..63
    const int slane = tid & 3;    // softmax lane 0..3

    const float* qbase = qkv + (size_t)(b * T_) * N_QKV + h * D_;         // q
    const float* kbase = qbase + C_;                                       // k
    const float* vbase = qbase + 2 * C_;                                   // v

    // Load Q tile (scaled by 1/sqrt(D))
#pragma unroll
    for (int i = 0; i < 4; i++) {
        int idx = tid + i * 256;          // 0..1023 (float4 units)
        int r   = idx >> 4;               // 0..63
        int c4  = idx & 15;               // 0..15
        float4 v = *(const float4*)(qbase + (size_t)(qt * 64 + r) * N_QKV + c4 * 4);
        float* dst = &Qs[r * QS_STRIDE + c4 * 4];
        dst[0] = v.x * SCALE; dst[1] = v.y * SCALE;
        dst[2] = v.z * SCALE; dst[3] = v.w * SCALE;
    }

    float acc[4][4];
#pragma unroll
    for (int i = 0; i < 4; i++)
#pragma unroll
        for (int j = 0; j < 4; j++) acc[i][j] = 0.0f;

    float m_i = -1e30f, l_i = 0.0f;   // per-softmax-row stats (replicated x4)

    for (int kt = 0; kt <= qt; kt++) {
        __syncthreads();   // previous PV done before overwriting K/V/S

        // Load K, V tiles
#pragma unroll
        for (int i = 0; i < 4; i++) {
            int idx = tid + i * 256;
            int r   = idx >> 4;
            int c4  = idx & 15;
            size_t grow = (size_t)(kt * 64 + r) * N_QKV;
            float4 kv = *(const float4*)(kbase + grow + c4 * 4);
            *(float4*)&Ks[r * QS_STRIDE + c4 * 4] = kv;
            float4 vv = *(const float4*)(vbase + grow + c4 * 4);
            *(float4*)&Vs[r * 64 + c4 * 4] = vv;
        }
        __syncthreads();

        // S = Q K^T  (scale already in Q)
        float s[4][4];
#pragma unroll
        for (int i = 0; i < 4; i++)
#pragma unroll
            for (int j = 0; j < 4; j++) s[i][j] = 0.0f;

#pragma unroll
        for (int dd = 0; dd < 16; dd++) {
            float4 q4[4], k4[4];
#pragma unroll
            for (int i = 0; i < 4; i++)
                q4[i] = *(const float4*)&Qs[(ty + 16 * i) * QS_STRIDE + dd * 4];
#pragma unroll
            for (int j = 0; j < 4; j++)
                k4[j] = *(const float4*)&Ks[(tx + 16 * j) * QS_STRIDE + dd * 4];
#pragma unroll
            for (int i = 0; i < 4; i++)
#pragma unroll
                for (int j = 0; j < 4; j++) {
                    s[i][j] = fmaf(q4[i].x, k4[j].x, s[i][j]);
                    s[i][j] = fmaf(q4[i].y, k4[j].y, s[i][j]);
                    s[i][j] = fmaf(q4[i].z, k4[j].z, s[i][j]);
                    s[i][j] = fmaf(q4[i].w, k4[j].w, s[i][j]);
                }
        }

        // Causal mask (diagonal tile only) + store S
        const bool diag = (kt == qt);
#pragma unroll
        for (int i = 0; i < 4; i++) {
            int r = ty + 16 * i;
#pragma unroll
            for (int j = 0; j < 4; j++) {
                int c = tx + 16 * j;
                float v = s[i][j];
                if (diag && c > r) v = -1e30f;
                Ss[r * QS_STRIDE + c] = v;
            }
        }
        __syncthreads();

        // Online softmax: 4 threads per row, 16 cols each
        {
            float sv[16];
            float mloc = -1e30f;
#pragma unroll
            for (int cc = 0; cc < 16; cc++) {
                sv[cc] = Ss[srow * QS_STRIDE + slane * 16 + cc];
                mloc = fmaxf(mloc, sv[cc]);
            }
            mloc = fmaxf(mloc, __shfl_xor_sync(0xffffffffu, mloc, 1));
            mloc = fmaxf(mloc, __shfl_xor_sync(0xffffffffu, mloc, 2));
            float m_new = fmaxf(m_i, mloc);
            float corr  = __expf(m_i - m_new);
            float psum  = 0.0f;
#pragma unroll
            for (int cc = 0; cc < 16; cc++) {
                float p = __expf(sv[cc] - m_new);
                psum += p;
                Ss[srow * QS_STRIDE + slane * 16 + cc] = p;
            }
            psum += __shfl_xor_sync(0xffffffffu, psum, 1);
            psum += __shfl_xor_sync(0xffffffffu, psum, 2);
            l_i = l_i * corr + psum;
            m_i = m_new;
            if (slane == 0) {
                c_s[srow] = corr;
                l_s[srow] = l_i;
            }
        }
        __syncthreads();

        // Rescale accumulator, then O += P V
        float cr[4];
#pragma unroll
        for (int i = 0; i < 4; i++) cr[i] = c_s[ty + 16 * i];
#pragma unroll
        for (int i = 0; i < 4; i++)
#pragma unroll
            for (int j = 0; j < 4; j++) acc[i][j] *= cr[i];

#pragma unroll
        for (int kk4 = 0; kk4 < 16; kk4++) {
            float4 p4[4];
#pragma unroll
            for (int i = 0; i < 4; i++)
                p4[i] = *(const float4*)&Ss[(ty + 16 * i) * QS_STRIDE + kk4 * 4];
#pragma unroll
            for (int q = 0; q < 4; q++) {
                float vj[4];
#pragma unroll
                for (int j = 0; j < 4; j++)
                    vj[j] = Vs[(kk4 * 4 + q) * 64 + tx + 16 * j];
                float pi[4];
                pi[0] = (q == 0) ? p4[0].x : (q == 1) ? p4[0].y : (q == 2) ? p4[0].z : p4[0].w;
                pi[1] = (q == 0) ? p4[1].x : (q == 1) ? p4[1].y : (q == 2) ? p4[1].z : p4[1].w;
                pi[2] = (q == 0) ? p4[2].x : (q == 1) ? p4[2].y : (q == 2) ? p4[2].z : p4[2].w;
                pi[3] = (q == 0) ? p4[3].x : (q == 1) ? p4[3].y : (q == 2) ? p4[3].z : p4[3].w;
#pragma unroll
                for (int i = 0; i < 4; i++)
#pragma unroll
                    for (int j = 0; j < 4; j++)
                        acc[i][j] = fmaf(pi[i], vj[j], acc[i][j]);
            }
        }
    }

    // Epilogue: divide by l, write [B,T,H*D]
#pragma unroll
    for (int i = 0; i < 4; i++) {
        int r = ty + 16 * i;
        float inv_l = 1.0f / l_s[r];
        size_t grow = (size_t)(b * T_ + qt * 64 + r) * C_ + h * D_;
#pragma unroll
        for (int j = 0; j < 4; j++)
            out[grow + tx + 16 * j] = acc[i][j] * inv_l;
    }
}

// ---------------------------------------------------------------------------
// Launch
// ---------------------------------------------------------------------------
extern "C" void kernel_launch(void* const* d_in, const int* in_sizes, int n_in,
                              void* d_out, int out_size)
{
    const float* x      = (const float*)d_in[0];
    const float* W_qkv  = (const float*)d_in[1];
    const float* b_qkv  = (const float*)d_in[2];
    const float* W_proj = (const float*)d_in[3];
    const float* b_proj = (const float*)d_in[4];
    float* out = (float*)d_out;

    float* qkv = nullptr;
    float* att = nullptr;
    cudaGetSymbolAddress((void**)&qkv, g_qkv);
    cudaGetSymbolAddress((void**)&att, g_att);

    dim3 blk(256);

    // 1) qkv = x @ W_qkv^T + b_qkv
    gemm_bias_kernel<<<dim3(N_QKV / 128, M_ / 128), blk>>>(
        x, W_qkv, b_qkv, qkv, M_, N_QKV, C_);

    // 2) flash attention
    size_t smem = FL_SMEM_FLOATS * sizeof(float);
    cudaFuncSetAttribute(flash_kernel,
                         cudaFuncAttributeMaxDynamicSharedMemorySize, (int)smem);
    flash_kernel<<<dim3(T_ / 64, B_ * H_), blk, smem>>>(qkv, att);

    // 3) out = att @ W_proj^T + b_proj
    gemm_bias_kernel<<<dim3(C_ / 128, M_ / 128), blk>>>(
        att, W_proj, b_proj, out, M_, C_, C_);
}

// round 2
// speedup vs baseline: 2.5644x; 2.5644x over previous
#include <cuda_runtime.h>
#include <math.h>

// ---------------------------------------------------------------------------
// Problem constants
// ---------------------------------------------------------------------------
#define B_    4
#define T_    2048
#define C_    1024
#define H_    16
#define D_    64
#define M_    (B_ * T_)        // 8192
#define N_QKV (3 * C_)         // 3072
#define SCALE 0.125f           // 1/sqrt(64)

__device__ float g_qkv[M_ * N_QKV];   // [8192, 3072]
__device__ float g_att[M_ * C_];      // [8192, 1024]

// ---------------------------------------------------------------------------
// Helpers: tf32 convert + m16n8k8 tf32 mma
// ---------------------------------------------------------------------------
__device__ __forceinline__ float t32(float x) {
    unsigned u;
    asm("cvt.rna.tf32.f32 %0, %1;" : "=r"(u) : "f"(x));
    return __uint_as_float(u);
}

__device__ __forceinline__ void mma_tf32(float* d,
                                         unsigned a0, unsigned a1, unsigned a2, unsigned a3,
                                         unsigned b0, unsigned b1) {
    asm volatile(
        "mma.sync.aligned.m16n8k8.row.col.f32.tf32.tf32.f32 "
        "{%0,%1,%2,%3}, {%4,%5,%6,%7}, {%8,%9}, {%0,%1,%2,%3};"
        : "+f"(d[0]), "+f"(d[1]), "+f"(d[2]), "+f"(d[3])
        : "r"(a0), "r"(a1), "r"(a2), "r"(a3), "r"(b0), "r"(b1));
}

__device__ __forceinline__ unsigned ldu(const float* p) { return __float_as_uint(*p); }

// ---------------------------------------------------------------------------
// TF32 GEMM: C[m,n] = sum_k A[m,k]*W[n,k] + bias[n]   (A @ W^T + b)
// 128x128 block tile, BK=16, 256 threads (8 warps), warp tile 32x64.
// smem operand layout [row][k], stride 20 -> conflict-free fragment loads.
// ---------------------------------------------------------------------------
#define GSTR 20

__global__ __launch_bounds__(256, 2)
void gemm_tf32_kernel(const float* __restrict__ A,
                      const float* __restrict__ W,
                      const float* __restrict__ bias,
                      float* __restrict__ Cc,
                      int M, int N, int K)
{
    __shared__ float As[128 * GSTR];
    __shared__ float Bs[128 * GSTR];

    const int tid  = threadIdx.x;
    const int warp = tid >> 5;
    const int lane = tid & 31;
    const int wm   = warp & 3;        // 0..3  (m direction, 32 rows each)
    const int wn   = warp >> 2;       // 0..1  (n direction, 64 cols each)
    const int g    = lane >> 2;       // group 0..7
    const int q    = lane & 3;        // 0..3
    const int bm   = blockIdx.y * 128;
    const int bn   = blockIdx.x * 128;

    float acc[2][8][4];
#pragma unroll
    for (int mt = 0; mt < 2; mt++)
#pragma unroll
        for (int nt = 0; nt < 8; nt++)
#pragma unroll
            for (int c = 0; c < 4; c++) acc[mt][nt][c] = 0.0f;

    const int lr  = tid >> 2;   // 0..63? no: tid/4 -> 0..63 ... see below
    const int lc4 = tid & 3;

    for (int k0 = 0; k0 < K; k0 += 16) {
        // Load 128x16 of A and W. 512 float4 each; 2 per thread per matrix.
#pragma unroll
        for (int i = 0; i < 2; i++) {
            int idx = tid + i * 256;
            int r   = idx >> 2;          // 0..127
            int c4  = idx & 3;           // 0..3
            float4 a = *(const float4*)(A + (size_t)(bm + r) * K + k0 + c4 * 4);
            float* da = &As[r * GSTR + c4 * 4];
            da[0] = t32(a.x); da[1] = t32(a.y); da[2] = t32(a.z); da[3] = t32(a.w);
            float4 w = *(const float4*)(W + (size_t)(bn + r) * K + k0 + c4 * 4);
            float* db = &Bs[r * GSTR + c4 * 4];
            db[0] = t32(w.x); db[1] = t32(w.y); db[2] = t32(w.z); db[3] = t32(w.w);
        }
        __syncthreads();

#pragma unroll
        for (int k8 = 0; k8 < 2; k8++) {
            const int kk = k8 * 8;
            unsigned aa[2][4];
#pragma unroll
            for (int mt = 0; mt < 2; mt++) {
                int rb = wm * 32 + mt * 16;
                aa[mt][0] = ldu(&As[(rb + g)     * GSTR + kk + q]);
                aa[mt][1] = ldu(&As[(rb + g + 8) * GSTR + kk + q]);
                aa[mt][2] = ldu(&As[(rb + g)     * GSTR + kk + q + 4]);
                aa[mt][3] = ldu(&As[(rb + g + 8) * GSTR + kk + q + 4]);
            }
            unsigned bb[8][2];
#pragma unroll
            for (int nt = 0; nt < 8; nt++) {
                int nb = wn * 64 + nt * 8 + g;
                bb[nt][0] = ldu(&Bs[nb * GSTR + kk + q]);
                bb[nt][1] = ldu(&Bs[nb * GSTR + kk + q + 4]);
            }
#pragma unroll
            for (int mt = 0; mt < 2; mt++)
#pragma unroll
                for (int nt = 0; nt < 8; nt++)
                    mma_tf32(acc[mt][nt], aa[mt][0], aa[mt][1], aa[mt][2], aa[mt][3],
                             bb[nt][0], bb[nt][1]);
        }
        __syncthreads();
    }

    // Epilogue: bias + float2 stores
    float2 bv[8];
#pragma unroll
    for (int nt = 0; nt < 8; nt++) {
        int col = bn + wn * 64 + nt * 8 + 2 * q;
        bv[nt].x = bias[col];
        bv[nt].y = bias[col + 1];
    }
#pragma unroll
    for (int mt = 0; mt < 2; mt++) {
        int row = bm + wm * 32 + mt * 16 + g;
#pragma unroll
        for (int nt = 0; nt < 8; nt++) {
            int col = bn + wn * 64 + nt * 8 + 2 * q;
            float2 v0 = make_float2(acc[mt][nt][0] + bv[nt].x, acc[mt][nt][1] + bv[nt].y);
            float2 v1 = make_float2(acc[mt][nt][2] + bv[nt].x, acc[mt][nt][3] + bv[nt].y);
            *(float2*)&Cc[(size_t)row * N + col]       = v0;
            *(float2*)&Cc[(size_t)(row + 8) * N + col] = v1;
        }
    }
}

// ---------------------------------------------------------------------------
// Flash attention with TF32 mma. BQ=BK=64, D=64. 8 warps (4 m x 2 n).
// Warp tile: 16 rows x 32 cols (of S and of O).
// Q/K/P stride 68 (4g+q bank pattern), V stride 72 (8q+g pattern).
// ---------------------------------------------------------------------------
#define QSTR 68
#define VSTR 72
#define FL_SMEM_FLOATS (3 * 64 * QSTR + 64 * VSTR + 256)

__global__ __launch_bounds__(256, 2)
void flash_tf32_kernel(const float* __restrict__ qkv, float* __restrict__ out)
{
    extern __shared__ float sm[];
    float* Qs     = sm;                      // [64][68]
    float* Ks     = Qs + 64 * QSTR;          // [64][68]
    float* Ps     = Ks + 64 * QSTR;          // [64][68]
    float* Vs     = Ps + 64 * QSTR;          // [64][72]
    float* redmax = Vs + 64 * VSTR;          // [2][64]
    float* redsum = redmax + 128;            // [2][64]

    const int qt   = (int)gridDim.x - 1 - (int)blockIdx.x;  // heavy tiles first
    const int bh   = blockIdx.y;
    const int b    = bh >> 4;
    const int h    = bh & 15;
    const int tid  = threadIdx.x;
    const int warp = tid >> 5;
    const int lane = tid & 31;
    const int wm   = warp >> 1;    // 0..3
    const int wn   = warp & 1;     // 0..1
    const int g    = lane >> 2;
    const int q    = lane & 3;
    const int r0   = wm * 16 + g;
    const int r1   = r0 + 8;

    const float* qb = qkv + (size_t)(b * T_) * N_QKV + h * D_;
    const float* kb = qb + C_;
    const float* vb = qb + 2 * C_;

    // Load + scale + tf32-round Q tile
#pragma unroll
    for (int i = 0; i < 4; i++) {
        int idx = tid + i * 256;
        int r   = idx >> 4;        // 0..63
        int c4  = idx & 15;        // 0..15
        float4 v = *(const float4*)(qb + (size_t)(qt * 64 + r) * N_QKV + c4 * 4);
        float* d = &Qs[r * QSTR + c4 * 4];
        d[0] = t32(v.x * SCALE); d[1] = t32(v.y * SCALE);
        d[2] = t32(v.z * SCALE); d[3] = t32(v.w * SCALE);
    }

    float o[4][4];
#pragma unroll
    for (int j = 0; j < 4; j++)
#pragma unroll
        for (int c = 0; c < 4; c++) o[j][c] = 0.0f;
    float m0 = -1e30f, m1 = -1e30f, l0 = 0.0f, l1 = 0.0f;

    for (int kt = 0; kt <= qt; kt++) {
        __syncthreads();   // prev PV done before K/V overwrite

        // Load K, V tiles (tf32-rounded)
#pragma unroll
        for (int i = 0; i < 4; i++) {
            int idx = tid + i * 256;
            int r   = idx >> 4;
            int c4  = idx & 15;
            size_t grow = (size_t)(kt * 64 + r) * N_QKV + c4 * 4;
            float4 kv = *(const float4*)(kb + grow);
            float* dk = &Ks[r * QSTR + c4 * 4];
            dk[0] = t32(kv.x); dk[1] = t32(kv.y); dk[2] = t32(kv.z); dk[3] = t32(kv.w);
            float4 vv = *(const float4*)(vb + grow);
            float* dv = &Vs[r * VSTR + c4 * 4];
            dv[0] = t32(vv.x); dv[1] = t32(vv.y); dv[2] = t32(vv.z); dv[3] = t32(vv.w);
        }
        __syncthreads();

        // S = Q K^T
        float s[4][4];
#pragma unroll
        for (int j = 0; j < 4; j++)
#pragma unroll
            for (int c = 0; c < 4; c++) s[j][c] = 0.0f;

#pragma unroll
        for (int k8 = 0; k8 < 8; k8++) {
            const int kk = k8 * 8;
            unsigned a0 = ldu(&Qs[r0 * QSTR + kk + q]);
            unsigned a1 = ldu(&Qs[r1 * QSTR + kk + q]);
            unsigned a2 = ldu(&Qs[r0 * QSTR + kk + q + 4]);
            unsigned a3 = ldu(&Qs[r1 * QSTR + kk + q + 4]);
#pragma unroll
            for (int j = 0; j < 4; j++) {
                int n = wn * 32 + j * 8 + g;
                unsigned b0 = ldu(&Ks[n * QSTR + kk + q]);
                unsigned b1 = ldu(&Ks[n * QSTR + kk + q + 4]);
                mma_tf32(s[j], a0, a1, a2, a3, b0, b1);
            }
        }

        // Causal mask on the diagonal tile
        if (kt == qt) {
#pragma unroll
            for (int j = 0; j < 4; j++) {
                int c = wn * 32 + j * 8 + 2 * q;
                if (c     > r0) s[j][0] = -1e30f;
                if (c + 1 > r0) s[j][1] = -1e30f;
                if (c     > r1) s[j][2] = -1e30f;
                if (c + 1 > r1) s[j][3] = -1e30f;
            }
        }

        // Row max over this warp's 32 cols
        float mx0 = -1e30f, mx1 = -1e30f;
#pragma unroll
        for (int j = 0; j < 4; j++) {
            mx0 = fmaxf(mx0, fmaxf(s[j][0], s[j][1]));
            mx1 = fmaxf(mx1, fmaxf(s[j][2], s[j][3]));
        }
        mx0 = fmaxf(mx0, __shfl_xor_sync(0xffffffffu, mx0, 1));
        mx0 = fmaxf(mx0, __shfl_xor_sync(0xffffffffu, mx0, 2));
        mx1 = fmaxf(mx1, __shfl_xor_sync(0xffffffffu, mx1, 1));
        mx1 = fmaxf(mx1, __shfl_xor_sync(0xffffffffu, mx1, 2));
        if (q == 0) {
            redmax[wn * 64 + r0] = mx0;
            redmax[wn * 64 + r1] = mx1;
        }
        __syncthreads();

        float rm0 = fmaxf(redmax[r0], redmax[64 + r0]);
        float rm1 = fmaxf(redmax[r1], redmax[64 + r1]);
        float mn0 = fmaxf(m0, rm0);
        float mn1 = fmaxf(m1, rm1);
        float cr0 = __expf(m0 - mn0);
        float cr1 = __expf(m1 - mn1);
        m0 = mn0; m1 = mn1;

        float sum0 = 0.0f, sum1 = 0.0f;
#pragma unroll
        for (int j = 0; j < 4; j++) {
            int c = wn * 32 + j * 8 + 2 * q;
            float p0 = __expf(s[j][0] - mn0);
            float p1 = __expf(s[j][1] - mn0);
            float p2 = __expf(s[j][2] - mn1);
            float p3 = __expf(s[j][3] - mn1);
            sum0 += p0 + p1;
            sum1 += p2 + p3;
            Ps[r0 * QSTR + c]     = t32(p0);
            Ps[r0 * QSTR + c + 1] = t32(p1);
            Ps[r1 * QSTR + c]     = t32(p2);
            Ps[r1 * QSTR + c + 1] = t32(p3);
        }
        sum0 += __shfl_xor_sync(0xffffffffu, sum0, 1);
        sum0 += __shfl_xor_sync(0xffffffffu, sum0, 2);
        sum1 += __shfl_xor_sync(0xffffffffu, sum1, 1);
        sum1 += __shfl_xor_sync(0xffffffffu, sum1, 2);
        if (q == 0) {
            redsum[wn * 64 + r0] = sum0;
            redsum[wn * 64 + r1] = sum1;
        }

        // Rescale O accumulator
#pragma unroll
        for (int j = 0; j < 4; j++) {
            o[j][0] *= cr0; o[j][1] *= cr0;
            o[j][2] *= cr1; o[j][3] *= cr1;
        }
        __syncthreads();

        l0 = l0 * cr0 + redsum[r0] + redsum[64 + r0];
        l1 = l1 * cr1 + redsum[r1] + redsum[64 + r1];

        // O += P V
#pragma unroll
        for (int k8 = 0; k8 < 8; k8++) {
            const int kk = k8 * 8;
            unsigned a0 = ldu(&Ps[r0 * QSTR + kk + q]);
            unsigned a1 = ldu(&Ps[r1 * QSTR + kk + q]);
            unsigned a2 = ldu(&Ps[r0 * QSTR + kk + q + 4]);
            unsigned a3 = ldu(&Ps[r1 * QSTR + kk + q + 4]);
#pragma unroll
            for (int j = 0; j < 4; j++) {
                int n = wn * 32 + j * 8 + g;
                unsigned b0 = ldu(&Vs[(kk + q)     * VSTR + n]);
                unsigned b1 = ldu(&Vs[(kk + q + 4) * VSTR + n]);
                mma_tf32(o[j], a0, a1, a2, a3, b0, b1);
            }
        }
    }

    // Epilogue: normalize, write [B,T,H*D]
    float il0 = 1.0f / l0;
    float il1 = 1.0f / l1;
    size_t row0 = (size_t)(b * T_ + qt * 64 + r0);
    size_t row1 = (size_t)(b * T_ + qt * 64 + r1);
#pragma unroll
    for (int j = 0; j < 4; j++) {
        int col = h * 64 + wn * 32 + j * 8 + 2 * q;
        *(float2*)&out[row0 * C_ + col] = make_float2(o[j][0] * il0, o[j][1] * il0);
        *(float2*)&out[row1 * C_ + col] = make_float2(o[j][2] * il1, o[j][3] * il1);
    }
}

// ---------------------------------------------------------------------------
// Launch
// ---------------------------------------------------------------------------
extern "C" void kernel_launch(void* const* d_in, const int* in_sizes, int n_in,
                              void* d_out, int out_size)
{
    const float* x      = (const float*)d_in[0];
    const float* W_qkv  = (const float*)d_in[1];
    const float* b_qkv  = (const float*)d_in[2];
    const float* W_proj = (const float*)d_in[3];
    const float* b_proj = (const float*)d_in[4];
    float* out = (float*)d_out;

    float* qkv = nullptr;
    float* att = nullptr;
    cudaGetSymbolAddress((void**)&qkv, g_qkv);
    cudaGetSymbolAddress((void**)&att, g_att);

    dim3 blk(256);

    // 1) qkv = x @ W_qkv^T + b_qkv
    gemm_tf32_kernel<<<dim3(N_QKV / 128, M_ / 128), blk>>>(
        x, W_qkv, b_qkv, qkv, M_, N_QKV, C_);

    // 2) flash attention
    size_t smem = FL_SMEM_FLOATS * sizeof(float);
    cudaFuncSetAttribute(flash_tf32_kernel,
                         cudaFuncAttributeMaxDynamicSharedMemorySize, (int)smem);
    flash_tf32_kernel<<<dim3(T_ / 64, B_ * H_), blk, smem>>>(qkv, att);

    // 3) out = att @ W_proj^T + b_proj
    gemm_tf32_kernel<<<dim3(C_ / 128, M_ / 128), blk>>>(
        att, W_proj, b_proj, out, M_, C_, C_);
}

// round 3
// speedup vs baseline: 3.4148x; 1.3316x over previous
#include <cuda_runtime.h>
#include <cuda_fp16.h>
#include <math.h>

// ---------------------------------------------------------------------------
// Problem constants
// ---------------------------------------------------------------------------
#define B_    4
#define T_    2048
#define C_    1024
#define H_    16
#define D_    64
#define M_    (B_ * T_)        // 8192
#define N_QKV (3 * C_)         // 3072

// Scratch (__device__ globals; allocation-free rule)
__device__ __half g_hx[M_ * C_];
__device__ __half g_hw1[N_QKV * C_];
__device__ __half g_hw2[C_ * C_];
__device__ __half g_qkv[(size_t)M_ * N_QKV];
__device__ __half g_att[M_ * C_];

// ---------------------------------------------------------------------------
// PTX helpers
// ---------------------------------------------------------------------------
__device__ __forceinline__ unsigned sptr(const void* p) {
    return (unsigned)__cvta_generic_to_shared(p);
}
__device__ __forceinline__ void ldsm4(unsigned& r0, unsigned& r1,
                                      unsigned& r2, unsigned& r3, unsigned a) {
    asm volatile("ldmatrix.sync.aligned.m8n8.x4.shared.b16 {%0,%1,%2,%3},[%4];"
                 : "=r"(r0), "=r"(r1), "=r"(r2), "=r"(r3) : "r"(a));
}
__device__ __forceinline__ void ldsm4t(unsigned& r0, unsigned& r1,
                                       unsigned& r2, unsigned& r3, unsigned a) {
    asm volatile("ldmatrix.sync.aligned.m8n8.x4.trans.shared.b16 {%0,%1,%2,%3},[%4];"
                 : "=r"(r0), "=r"(r1), "=r"(r2), "=r"(r3) : "r"(a));
}
__device__ __forceinline__ void mma16816(float* d,
                                         unsigned a0, unsigned a1, unsigned a2, unsigned a3,
                                         unsigned b0, unsigned b1) {
    asm volatile(
        "mma.sync.aligned.m16n8k16.row.col.f32.f16.f16.f32 "
        "{%0,%1,%2,%3},{%4,%5,%6,%7},{%8,%9},{%0,%1,%2,%3};"
        : "+f"(d[0]), "+f"(d[1]), "+f"(d[2]), "+f"(d[3])
        : "r"(a0), "r"(a1), "r"(a2), "r"(a3), "r"(b0), "r"(b1));
}

// ---------------------------------------------------------------------------
// fp32 -> fp16 convert (one thread = 4 elements)
// ---------------------------------------------------------------------------
__global__ void f2h_kernel(const float* __restrict__ in, __half* __restrict__ out, int n4) {
    int i = blockIdx.x * blockDim.x + threadIdx.x;
    if (i < n4) {
        float4 v = ((const float4*)in)[i];
        __half2 h0 = __floats2half2_rn(v.x, v.y);
        __half2 h1 = __floats2half2_rn(v.z, v.w);
        uint2 u;
        u.x = *(unsigned*)&h0;
        u.y = *(unsigned*)&h1;
        ((uint2*)out)[i] = u;
    }
}

// ---------------------------------------------------------------------------
// FP16 GEMM: C[m,n] = sum_k A[m,k]*W[n,k] + bias[n]
// Block 128x128, BK=32, 256 threads (8 warps), warp tile 32x64, mma m16n8k16.
// smem rows padded to 40 halves (80B) -> conflict-free LDSM & stores.
// Double-buffered smem, register-staged gmem loads.
// ---------------------------------------------------------------------------
#define SR 40

template <bool HALF_OUT>
__global__ __launch_bounds__(256, 2)
void gemm_f16_kernel(const __half* __restrict__ A,
                     const __half* __restrict__ W,
                     const float* __restrict__ bias,
                     void* __restrict__ Cc,
                     int M, int N, int K)
{
    __shared__ __half As[2][128 * SR];
    __shared__ __half Bs[2][128 * SR];

    const int tid  = threadIdx.x;
    const int warp = tid >> 5;
    const int lane = tid & 31;
    const int wm   = warp & 3;      // 4 warps along m (32 rows each)
    const int wn   = warp >> 2;     // 2 warps along n (64 cols each)
    const int g    = lane >> 2;
    const int q    = lane & 3;
    const int la   = lane & 7;
    const int lb   = (lane >> 3) & 1;
    const int lc   = lane >> 4;
    const int bm   = blockIdx.y * 128;
    const int bn   = blockIdx.x * 128;

    // Load mapping: row rl = (tid&7)+8*(tid>>5) in 0..63; chunk cl = (tid>>3)&3
    const int rl = (tid & 7) + 8 * (tid >> 5);
    const int cl = (tid >> 3) & 3;

    float acc[2][8][4];
#pragma unroll
    for (int mt = 0; mt < 2; mt++)
#pragma unroll
        for (int nt = 0; nt < 8; nt++)
#pragma unroll
            for (int c = 0; c < 4; c++) acc[mt][nt][c] = 0.0f;

    uint4 sa0, sa1, sb0, sb1;
    const int nk = K >> 5;   // BK=32

#define GLOAD(k0)                                                              \
    do {                                                                       \
        sa0 = *(const uint4*)(A + (size_t)(bm + rl) * K + (k0) + 8 * cl);      \
        sa1 = *(const uint4*)(A + (size_t)(bm + rl + 64) * K + (k0) + 8 * cl); \
        sb0 = *(const uint4*)(W + (size_t)(bn + rl) * K + (k0) + 8 * cl);      \
        sb1 = *(const uint4*)(W + (size_t)(bn + rl + 64) * K + (k0) + 8 * cl); \
    } while (0)

#define SSTORE(buf)                                                            \
    do {                                                                       \
        *(uint4*)&As[buf][rl * SR + 8 * cl]        = sa0;                      \
        *(uint4*)&As[buf][(rl + 64) * SR + 8 * cl] = sa1;                      \
        *(uint4*)&Bs[buf][rl * SR + 8 * cl]        = sb0;                      \
        *(uint4*)&Bs[buf][(rl + 64) * SR + 8 * cl] = sb1;                      \
    } while (0)

    GLOAD(0);
    SSTORE(0);
    __syncthreads();

    for (int c = 0; c < nk; c++) {
        if (c + 1 < nk) GLOAD((c + 1) * 32);

        const __half* as = As[c & 1];
        const __half* bs = Bs[c & 1];
        const unsigned abase = sptr(as);
        const unsigned bbase = sptr(bs);

#pragma unroll
        for (int kk = 0; kk < 2; kk++) {
            unsigned a[2][4];
#pragma unroll
            for (int mt = 0; mt < 2; mt++) {
                int row = wm * 32 + mt * 16 + lb * 8 + la;
                int ch  = 2 * kk + lc;
                ldsm4(a[mt][0], a[mt][1], a[mt][2], a[mt][3],
                      abase + (row * SR + ch * 8) * 2);
            }
            unsigned bfr[4][4];
#pragma unroll
            for (int ntp = 0; ntp < 4; ntp++) {
                int row = wn * 64 + ntp * 16 + lc * 8 + la;
                int ch  = 2 * kk + lb;
                ldsm4(bfr[ntp][0], bfr[ntp][1], bfr[ntp][2], bfr[ntp][3],
                      bbase + (row * SR + ch * 8) * 2);
            }
#pragma unroll
            for (int mt = 0; mt < 2; mt++)
#pragma unroll
                for (int ntp = 0; ntp < 4; ntp++) {
                    mma16816(acc[mt][2 * ntp],     a[mt][0], a[mt][1], a[mt][2], a[mt][3],
                             bfr[ntp][0], bfr[ntp][1]);
                    mma16816(acc[mt][2 * ntp + 1], a[mt][0], a[mt][1], a[mt][2], a[mt][3],
                             bfr[ntp][2], bfr[ntp][3]);
                }
        }

        if (c + 1 < nk) SSTORE((c + 1) & 1);
        __syncthreads();
    }

    // Epilogue: bias + store
    float2 bv[8];
#pragma unroll
    for (int nt = 0; nt < 8; nt++) {
        int col = bn + wn * 64 + nt * 8 + 2 * q;
        bv[nt].x = bias[col];
        bv[nt].y = bias[col + 1];
    }
#pragma unroll
    for (int mt = 0; mt < 2; mt++) {
        int row = bm + wm * 32 + mt * 16 + g;
#pragma unroll
        for (int nt = 0; nt < 8; nt++) {
            int col = bn + wn * 64 + nt * 8 + 2 * q;
            float x0 = acc[mt][nt][0] + bv[nt].x;
            float y0 = acc[mt][nt][1] + bv[nt].y;
            float x1 = acc[mt][nt][2] + bv[nt].x;
            float y1 = acc[mt][nt][3] + bv[nt].y;
            if (HALF_OUT) {
                __half* O = (__half*)Cc;
                __half2 h0 = __floats2half2_rn(x0, y0);
                __half2 h1 = __floats2half2_rn(x1, y1);
                *(__half2*)&O[(size_t)row * N + col]       = h0;
                *(__half2*)&O[(size_t)(row + 8) * N + col] = h1;
            } else {
                float* O = (float*)Cc;
                *(float2*)&O[(size_t)row * N + col]       = make_float2(x0, y0);
                *(float2*)&O[(size_t)(row + 8) * N + col] = make_float2(x1, y1);
            }
        }
    }
#undef GLOAD
#undef SSTORE
}

// ---------------------------------------------------------------------------
// Flash attention, fp16 mma. BQ=BK=64, D=64. 8 warps (4 m x 2 n).
// Warp tile: 16 q-rows x 32 cols. All smem tiles stride 72 halves (144B).
// ---------------------------------------------------------------------------
#define FSTR 72
#define FL_SMEM_BYTES (4 * 64 * FSTR * 2 + 256 * 4)

__global__ __launch_bounds__(256, 2)
void flash_f16_kernel(const __half* __restrict__ qkv, __half* __restrict__ out)
{
    extern __shared__ __half smh[];
    __half* Qs = smh;                  // [64][72]
    __half* Ks = Qs + 64 * FSTR;       // [64][72]
    __half* Vs = Ks + 64 * FSTR;       // [64][72]
    __half* Ps = Vs + 64 * FSTR;       // [64][72]
    float* redmax = (float*)(Ps + 64 * FSTR);   // [2][64]
    float* redsum = redmax + 128;               // [2][64]

    const int qt   = (int)gridDim.x - 1 - (int)blockIdx.x;  // heavy tiles first
    const int bh   = blockIdx.y;
    const int b    = bh >> 4;
    const int h    = bh & 15;
    const int tid  = threadIdx.x;
    const int warp = tid >> 5;
    const int lane = tid & 31;
    const int wm   = warp >> 1;    // 0..3
    const int wn   = warp & 1;     // 0..1
    const int g    = lane >> 2;
    const int q    = lane & 3;
    const int la   = lane & 7;
    const int lb   = (lane >> 3) & 1;
    const int lc   = lane >> 4;
    const int r0   = wm * 16 + g;
    const int r1   = r0 + 8;

    const __half* qb = qkv + (size_t)(b * T_) * N_QKV + h * D_;
    const __half* kb = qb + C_;
    const __half* vb = qb + 2 * C_;

    // Load mapping: 64 rows x 8 chunks of 8 halves. 2 per thread.
    const int frl = (tid & 7) + 8 * (tid >> 6);    // 0..31
    const int fcl = (tid >> 3) & 7;                // 0..7

    // Load Q tile, scaled by 1/8 (exact in fp16)
    const __half2 hs = __floats2half2_rn(0.125f, 0.125f);
#pragma unroll
    for (int i = 0; i < 2; i++) {
        int r = frl + 32 * i;
        uint4 v = *(const uint4*)(qb + (size_t)(qt * 64 + r) * N_QKV + 8 * fcl);
        __half2* p = (__half2*)&v;
        p[0] = __hmul2(p[0], hs); p[1] = __hmul2(p[1], hs);
        p[2] = __hmul2(p[2], hs); p[3] = __hmul2(p[3], hs);
        *(uint4*)&Qs[r * FSTR + 8 * fcl] = v;
    }

    float o[4][4];
#pragma unroll
    for (int j = 0; j < 4; j++)
#pragma unroll
        for (int c = 0; c < 4; c++) o[j][c] = 0.0f;
    float m0 = -1e30f, m1 = -1e30f, l0 = 0.0f, l1 = 0.0f;

    const unsigned qsb = sptr(Qs);
    const unsigned ksb = sptr(Ks);
    const unsigned vsb = sptr(Vs);
    const unsigned psb = sptr(Ps);

    for (int kt = 0; kt <= qt; kt++) {
        __syncthreads();   // prev PV reads done before K/V overwrite

        // Load K, V tiles
#pragma unroll
        for (int i = 0; i < 2; i++) {
            int r = frl + 32 * i;
            size_t grow = (size_t)(kt * 64 + r) * N_QKV + 8 * fcl;
            *(uint4*)&Ks[r * FSTR + 8 * fcl] = *(const uint4*)(kb + grow);
            *(uint4*)&Vs[r * FSTR + 8 * fcl] = *(const uint4*)(vb + grow);
        }
        __syncthreads();

        // S = Q K^T
        float s[4][4];
#pragma unroll
        for (int j = 0; j < 4; j++)
#pragma unroll
            for (int c = 0; c < 4; c++) s[j][c] = 0.0f;

#pragma unroll
        for (int kk = 0; kk < 4; kk++) {
            unsigned a0, a1, a2, a3;
            {
                int row = wm * 16 + lb * 8 + la;
                int ch  = 2 * kk + lc;
                ldsm4(a0, a1, a2, a3, qsb + (row * FSTR + ch * 8) * 2);
            }
#pragma unroll
            for (int ntp = 0; ntp < 2; ntp++) {
                unsigned b0, b1, b2, b3;
                int row = wn * 32 + ntp * 16 + lc * 8 + la;
                int ch  = 2 * kk + lb;
                ldsm4(b0, b1, b2, b3, ksb + (row * FSTR + ch * 8) * 2);
                mma16816(s[2 * ntp],     a0, a1, a2, a3, b0, b1);
                mma16816(s[2 * ntp + 1], a0, a1, a2, a3, b2, b3);
            }
        }

        // Causal mask on diagonal tile
        if (kt == qt) {
#pragma unroll
            for (int j = 0; j < 4; j++) {
                int c = wn * 32 + j * 8 + 2 * q;
                if (c     > r0) s[j][0] = -1e30f;
                if (c + 1 > r0) s[j][1] = -1e30f;
                if (c     > r1) s[j][2] = -1e30f;
                if (c + 1 > r1) s[j][3] = -1e30f;
            }
        }

        // Row max over this warp's 32 cols
        float mx0 = -1e30f, mx1 = -1e30f;
#pragma unroll
        for (int j = 0; j < 4; j++) {
            mx0 = fmaxf(mx0, fmaxf(s[j][0], s[j][1]));
            mx1 = fmaxf(mx1, fmaxf(s[j][2], s[j][3]));
        }
        mx0 = fmaxf(mx0, __shfl_xor_sync(0xffffffffu, mx0, 1));
        mx0 = fmaxf(mx0, __shfl_xor_sync(0xffffffffu, mx0, 2));
        mx1 = fmaxf(mx1, __shfl_xor_sync(0xffffffffu, mx1, 1));
        mx1 = fmaxf(mx1, __shfl_xor_sync(0xffffffffu, mx1, 2));
        if (q == 0) {
            redmax[wn * 64 + r0] = mx0;
            redmax[wn * 64 + r1] = mx1;
        }
        __syncthreads();

        float mn0 = fmaxf(m0, fmaxf(redmax[r0], redmax[64 + r0]));
        float mn1 = fmaxf(m1, fmaxf(redmax[r1], redmax[64 + r1]));
        float cr0 = __expf(m0 - mn0);
        float cr1 = __expf(m1 - mn1);
        m0 = mn0; m1 = mn1;

        float sum0 = 0.0f, sum1 = 0.0f;
#pragma unroll
        for (int j = 0; j < 4; j++) {
            int c = wn * 32 + j * 8 + 2 * q;
            float p0 = __expf(s[j][0] - mn0);
            float p1 = __expf(s[j][1] - mn0);
            float p2 = __expf(s[j][2] - mn1);
            float p3 = __expf(s[j][3] - mn1);
            sum0 += p0 + p1;
            sum1 += p2 + p3;
            *(__half2*)&Ps[r0 * FSTR + c] = __floats2half2_rn(p0, p1);
            *(__half2*)&Ps[r1 * FSTR + c] = __floats2half2_rn(p2, p3);
        }
        sum0 += __shfl_xor_sync(0xffffffffu, sum0, 1);
        sum0 += __shfl_xor_sync(0xffffffffu, sum0, 2);
        sum1 += __shfl_xor_sync(0xffffffffu, sum1, 1);
        sum1 += __shfl_xor_sync(0xffffffffu, sum1, 2);
        if (q == 0) {
            redsum[wn * 64 + r0] = sum0;
            redsum[wn * 64 + r1] = sum1;
        }

        // Rescale O accumulator
#pragma unroll
        for (int j = 0; j < 4; j++) {
            o[j][0] *= cr0; o[j][1] *= cr0;
            o[j][2] *= cr1; o[j][3] *= cr1;
        }
        __syncthreads();

        l0 = l0 * cr0 + redsum[r0] + redsum[64 + r0];
        l1 = l1 * cr1 + redsum[r1] + redsum[64 + r1];

        // O += P V
#pragma unroll
        for (int kkv = 0; kkv < 4; kkv++) {
            unsigned a0, a1, a2, a3;
            {
                int row = wm * 16 + lb * 8 + la;
                int ch  = 2 * kkv + lc;
                ldsm4(a0, a1, a2, a3, psb + (row * FSTR + ch * 8) * 2);
            }
#pragma unroll
            for (int ntp = 0; ntp < 2; ntp++) {
                unsigned b0, b1, b2, b3;
                int row = kkv * 16 + lb * 8 + la;
                int ch  = 4 * wn + 2 * ntp + lc;
                ldsm4t(b0, b1, b2, b3, vsb + (row * FSTR + ch * 8) * 2);
                mma16816(o[2 * ntp],     a0, a1, a2, a3, b0, b1);
                mma16816(o[2 * ntp + 1], a0, a1, a2, a3, b2, b3);
            }
        }
    }

    // Epilogue: normalize, write half to [B,T,H*D]
    float il0 = 1.0f / l0;
    float il1 = 1.0f / l1;
    size_t row0 = (size_t)(b * T_ + qt * 64 + r0);
    size_t row1 = (size_t)(b * T_ + qt * 64 + r1);
#pragma unroll
    for (int j = 0; j < 4; j++) {
        int col = h * 64 + wn * 32 + j * 8 + 2 * q;
        *(__half2*)&out[row0 * C_ + col] = __floats2half2_rn(o[j][0] * il0, o[j][1] * il0);
        *(__half2*)&out[row1 * C_ + col] = __floats2half2_rn(o[j][2] * il1, o[j][3] * il1);
    }
}

// ---------------------------------------------------------------------------
// Launch
// ---------------------------------------------------------------------------
extern "C" void kernel_launch(void* const* d_in, const int* in_sizes, int n_in,
                              void* d_out, int out_size)
{
    const float* x      = (const float*)d_in[0];
    const float* W_qkv  = (const float*)d_in[1];
    const float* b_qkv  = (const float*)d_in[2];
    const float* W_proj = (const float*)d_in[3];
    const float* b_proj = (const float*)d_in[4];
    float* out = (float*)d_out;

    __half *hx, *hw1, *hw2, *qkv, *att;
    cudaGetSymbolAddress((void**)&hx,  g_hx);
    cudaGetSymbolAddress((void**)&hw1, g_hw1);
    cudaGetSymbolAddress((void**)&hw2, g_hw2);
    cudaGetSymbolAddress((void**)&qkv, g_qkv);
    cudaGetSymbolAddress((void**)&att, g_att);

    // 0) fp32 -> fp16 converts
    f2h_kernel<<<(M_ * C_ / 4 + 255) / 256, 256>>>(x, hx, M_ * C_ / 4);
    f2h_kernel<<<(N_QKV * C_ / 4 + 255) / 256, 256>>>(W_qkv, hw1, N_QKV * C_ / 4);
    f2h_kernel<<<(C_ * C_ / 4 + 255) / 256, 256>>>(W_proj, hw2, C_ * C_ / 4);

    dim3 blk(256);

    // 1) qkv = x @ W_qkv^T + b_qkv   (half out)
    gemm_f16_kernel<true><<<dim3(N_QKV / 128, M_ / 128), blk>>>(
        hx, hw1, b_qkv, qkv, M_, N_QKV, C_);

    // 2) flash attention (half in, half out)
    cudaFuncSetAttribute(flash_f16_kernel,
                         cudaFuncAttributeMaxDynamicSharedMemorySize, FL_SMEM_BYTES);
    flash_f16_kernel<<<dim3(T_ / 64, B_ * H_), blk, FL_SMEM_BYTES>>>(qkv, att);

    // 3) out = att @ W_proj^T + b_proj   (float out)
    gemm_f16_kernel<false><<<dim3(C_ / 128, M_ / 128), blk>>>(
        att, hw2, b_proj, out, M_, C_, C_);
}

// round 6
// speedup vs baseline: 4.7718x; 1.3974x over previous
#include <cuda_runtime.h>
#include <cuda.h>
#include <cuda_fp16.h>
#include <math.h>
#include <stdint.h>

// ---------------------------------------------------------------------------
// Problem constants
// ---------------------------------------------------------------------------
#define B_    4
#define T_    2048
#define C_    1024
#define H_    16
#define D_    64
#define M_    (B_ * T_)        // 8192
#define N_QKV (3 * C_)         // 3072

// Scratch (__device__ globals; allocation-free rule)
__device__ __half g_hx[M_ * C_];
__device__ __half g_hw1[N_QKV * C_];
__device__ __half g_hw2[C_ * C_];
__device__ __half g_qkv[(size_t)M_ * N_QKV];
__device__ __half g_att[M_ * C_];

// ---------------------------------------------------------------------------
// PTX helpers
// ---------------------------------------------------------------------------
__device__ __forceinline__ unsigned sptr(const void* p) {
    return (unsigned)__cvta_generic_to_shared(p);
}
__device__ __forceinline__ void ldsm4(unsigned& r0, unsigned& r1,
                                      unsigned& r2, unsigned& r3, unsigned a) {
    asm volatile("ldmatrix.sync.aligned.m8n8.x4.shared.b16 {%0,%1,%2,%3},[%4];"
                 : "=r"(r0), "=r"(r1), "=r"(r2), "=r"(r3) : "r"(a));
}
__device__ __forceinline__ void ldsm4t(unsigned& r0, unsigned& r1,
                                       unsigned& r2, unsigned& r3, unsigned a) {
    asm volatile("ldmatrix.sync.aligned.m8n8.x4.trans.shared.b16 {%0,%1,%2,%3},[%4];"
                 : "=r"(r0), "=r"(r1), "=r"(r2), "=r"(r3) : "r"(a));
}
__device__ __forceinline__ void mma16816(float* d,
                                         unsigned a0, unsigned a1, unsigned a2, unsigned a3,
                                         unsigned b0, unsigned b1) {
    asm volatile(
        "mma.sync.aligned.m16n8k16.row.col.f32.f16.f16.f32 "
        "{%0,%1,%2,%3},{%4,%5,%6,%7},{%8,%9},{%0,%1,%2,%3};"
        : "+f"(d[0]), "+f"(d[1]), "+f"(d[2]), "+f"(d[3])
        : "r"(a0), "r"(a1), "r"(a2), "r"(a3), "r"(b0), "r"(b1));
}
__device__ __forceinline__ void mbar_init(unsigned a, unsigned cnt) {
    asm volatile("mbarrier.init.shared.b64 [%0], %1;" :: "r"(a), "r"(cnt) : "memory");
}
__device__ __forceinline__ void mbar_expect(unsigned a, unsigned bytes) {
    asm volatile("mbarrier.arrive.expect_tx.shared.b64 _, [%0], %1;"
                 :: "r"(a), "r"(bytes) : "memory");
}
__device__ __forceinline__ void mbar_arrive(unsigned a) {
    asm volatile("mbarrier.arrive.shared.b64 _, [%0];" :: "r"(a) : "memory");
}
__device__ __forceinline__ void mbar_wait(unsigned a, unsigned parity) {
    asm volatile(
        "{\n\t.reg .pred P;\n\t"
        "W%=:\n\t"
        "mbarrier.try_wait.parity.acquire.cta.shared::cta.b64 P, [%0], %1, 0x989680;\n\t"
        "@P bra.uni D%=;\n\t"
        "bra.uni W%=;\n\t"
        "D%=:\n\t}"
        :: "r"(a), "r"(parity) : "memory");
}
__device__ __forceinline__ void tma3d(unsigned dst, const void* tm, int x, int y, unsigned mbar) {
    asm volatile(
        "cp.async.bulk.tensor.3d.shared::cta.global.tile.mbarrier::complete_tx::bytes "
        "[%0], [%1, {%2, %3, %4}], [%5];"
        :: "r"(dst), "l"(tm), "r"(x), "r"(y), "r"(0), "r"(mbar) : "memory");
}
__device__ __forceinline__ void fence_async_shared() {
    asm volatile("fence.proxy.async.shared::cta;" ::: "memory");
}

// ---------------------------------------------------------------------------
// fp32 -> fp16 convert
// ---------------------------------------------------------------------------
__global__ void f2h_kernel(const float* __restrict__ in, __half* __restrict__ out, int n4) {
    int i = blockIdx.x * blockDim.x + threadIdx.x;
    if (i < n4) {
        float4 v = ((const float4*)in)[i];
        __half2 h0 = __floats2half2_rn(v.x, v.y);
        __half2 h1 = __floats2half2_rn(v.z, v.w);
        uint2 u;
        u.x = *(unsigned*)&h0;
        u.y = *(unsigned*)&h1;
        ((uint2*)out)[i] = u;
    }
}

// ---------------------------------------------------------------------------
// TMA-fed HMMA GEMM: C[m,n] = sum_k A[m,k]*W[n,k] + bias[n], K=1024.
// 128x128 tile, BK=64 (TMA box 128x64 halves, SW128), 3-stage ring.
// Hardened: __syncthreads before empty-arrive; fence.proxy.async before refill.
// ---------------------------------------------------------------------------
#define NSTAGE   3
#define ABYTES   (128 * 64 * 2)        // 16 KB per operand per stage
#define STAGEB   (2 * ABYTES)          // 32 KB
#define NKCHUNK  16                    // K=1024 / 64
#define GEMM_DSMEM (NSTAGE * STAGEB + 1024)

template <bool HALF_OUT>
__global__ __launch_bounds__(256)
void gemm_tma_kernel(const __grid_constant__ CUtensorMap tmA,
                     const __grid_constant__ CUtensorMap tmW,
                     const float* __restrict__ bias,
                     void* __restrict__ Cc, int N)
{
    extern __shared__ char dsm_raw[];
    __shared__ __align__(8) unsigned long long s_mbar[2 * NSTAGE];

    char* smb = (char*)(((uintptr_t)dsm_raw + 1023) & ~(uintptr_t)1023);
    const unsigned base = sptr(smb);

    const int tid  = threadIdx.x;
    const int warp = tid >> 5;
    const int lane = tid & 31;
    const int wm   = warp & 3;      // 4 warps along m (32 rows each)
    const int wn   = warp >> 2;     // 2 warps along n (64 cols each)
    const int g    = lane >> 2;
    const int q    = lane & 3;
    const int la   = lane & 7;
    const int lb   = (lane >> 3) & 1;
    const int lc   = lane >> 4;
    const int bm   = blockIdx.y * 128;
    const int bn   = blockIdx.x * 128;

    unsigned mf[NSTAGE], me[NSTAGE];
#pragma unroll
    for (int s = 0; s < NSTAGE; s++) {
        mf[s] = sptr(&s_mbar[s]);
        me[s] = sptr(&s_mbar[NSTAGE + s]);
    }

    if (tid == 0) {
#pragma unroll
        for (int s = 0; s < NSTAGE; s++) {
            mbar_init(mf[s], 1);
            mbar_init(me[s], 1);
        }
    }
    __syncthreads();

    // Prologue: fill all stages
    if (tid == 0) {
#pragma unroll
        for (int s = 0; s < NSTAGE; s++) {
            mbar_expect(mf[s], STAGEB);
            tma3d(base + s * STAGEB,          &tmA, s * 64, bm, mf[s]);
            tma3d(base + s * STAGEB + ABYTES, &tmW, s * 64, bn, mf[s]);
        }
    }

    float acc[2][8][4];
#pragma unroll
    for (int mt = 0; mt < 2; mt++)
#pragma unroll
        for (int nt = 0; nt < 8; nt++)
#pragma unroll
            for (int c = 0; c < 4; c++) acc[mt][nt][c] = 0.0f;

    for (int c = 0; c < NKCHUNK; c++) {
        const int s = c % NSTAGE;
        const unsigned ph = (unsigned)((c / NSTAGE) & 1);
        mbar_wait(mf[s], ph);

        const unsigned abase = base + s * STAGEB;
        const unsigned bbase = abase + ABYTES;

#pragma unroll
        for (int kk = 0; kk < 4; kk++) {
            unsigned a[2][4];
#pragma unroll
            for (int mt = 0; mt < 2; mt++) {
                int row = wm * 32 + mt * 16 + lb * 8 + la;
                int ch  = (2 * kk + lc) ^ (row & 7);
                ldsm4(a[mt][0], a[mt][1], a[mt][2], a[mt][3],
                      abase + row * 128 + ch * 16);
            }
            unsigned bfr[4][4];
#pragma unroll
            for (int ntp = 0; ntp < 4; ntp++) {
                int row = wn * 64 + ntp * 16 + lc * 8 + la;
                int ch  = (2 * kk + lb) ^ (row & 7);
                ldsm4(bfr[ntp][0], bfr[ntp][1], bfr[ntp][2], bfr[ntp][3],
                      bbase + row * 128 + ch * 16);
            }
#pragma unroll
            for (int mt = 0; mt < 2; mt++)
#pragma unroll
                for (int ntp = 0; ntp < 4; ntp++) {
                    mma16816(acc[mt][2 * ntp],     a[mt][0], a[mt][1], a[mt][2], a[mt][3],
                             bfr[ntp][0], bfr[ntp][1]);
                    mma16816(acc[mt][2 * ntp + 1], a[mt][0], a[mt][1], a[mt][2], a[mt][3],
                             bfr[ntp][2], bfr[ntp][3]);
                }
        }

        // All threads' ldmatrix reads of stage s are done at this barrier.
        __syncthreads();

        if (tid == 0) {
            const int cn = c + NSTAGE;
            if (cn < NKCHUNK) {
                fence_async_shared();    // order prior generic reads vs async writes
                mbar_expect(mf[s], STAGEB);
                tma3d(abase, &tmA, cn * 64, bm, mf[s]);
                tma3d(bbase, &tmW, cn * 64, bn, mf[s]);
            }
        }
    }

    // Epilogue: bias + store
    float2 bv[8];
#pragma unroll
    for (int nt = 0; nt < 8; nt++) {
        int col = bn + wn * 64 + nt * 8 + 2 * q;
        bv[nt].x = bias[col];
        bv[nt].y = bias[col + 1];
    }
#pragma unroll
    for (int mt = 0; mt < 2; mt++) {
        int row = bm + wm * 32 + mt * 16 + g;
#pragma unroll
        for (int nt = 0; nt < 8; nt++) {
            int col = bn + wn * 64 + nt * 8 + 2 * q;
            float x0 = acc[mt][nt][0] + bv[nt].x;
            float y0 = acc[mt][nt][1] + bv[nt].y;
            float x1 = acc[mt][nt][2] + bv[nt].x;
            float y1 = acc[mt][nt][3] + bv[nt].y;
            if (HALF_OUT) {
                __half* O = (__half*)Cc;
                *(__half2*)&O[(size_t)row * N + col]       = __floats2half2_rn(x0, y0);
                *(__half2*)&O[(size_t)(row + 8) * N + col] = __floats2half2_rn(x1, y1);
            } else {
                float* O = (float*)Cc;
                *(float2*)&O[(size_t)row * N + col]       = make_float2(x0, y0);
                *(float2*)&O[(size_t)(row + 8) * N + col] = make_float2(x1, y1);
            }
        }
    }
}

// ---------------------------------------------------------------------------
// Flash attention, fp16 mma — ROUND-3 VERSION VERBATIM (known good).
// BQ=BK=64, D=64. 8 warps (4 m x 2 n). All smem tiles stride 72 halves.
// ---------------------------------------------------------------------------
#define FSTR 72
#define FL_SMEM_BYTES (4 * 64 * FSTR * 2 + 256 * 4)

__global__ __launch_bounds__(256, 2)
void flash_f16_kernel(const __half* __restrict__ qkv, __half* __restrict__ out)
{
    extern __shared__ __half smh[];
    __half* Qs = smh;
    __half* Ks = Qs + 64 * FSTR;
    __half* Vs = Ks + 64 * FSTR;
    __half* Ps = Vs + 64 * FSTR;
    float* redmax = (float*)(Ps + 64 * FSTR);
    float* redsum = redmax + 128;

    const int qt   = (int)gridDim.x - 1 - (int)blockIdx.x;
    const int bh   = blockIdx.y;
    const int b    = bh >> 4;
    const int h    = bh & 15;
    const int tid  = threadIdx.x;
    const int warp = tid >> 5;
    const int lane = tid & 31;
    const int wm   = warp >> 1;
    const int wn   = warp & 1;
    const int g    = lane >> 2;
    const int q    = lane & 3;
    const int la   = lane & 7;
    const int lb   = (lane >> 3) & 1;
    const int lc   = lane >> 4;
    const int r0   = wm * 16 + g;
    const int r1   = r0 + 8;

    const __half* qb = qkv + (size_t)(b * T_) * N_QKV + h * D_;
    const __half* kb = qb + C_;
    const __half* vb = qb + 2 * C_;

    const int frl = (tid & 7) + 8 * (tid >> 6);
    const int fcl = (tid >> 3) & 7;

    const __half2 hs = __floats2half2_rn(0.125f, 0.125f);
#pragma unroll
    for (int i = 0; i < 2; i++) {
        int r = frl + 32 * i;
        uint4 v = *(const uint4*)(qb + (size_t)(qt * 64 + r) * N_QKV + 8 * fcl);
        __half2* p = (__half2*)&v;
        p[0] = __hmul2(p[0], hs); p[1] = __hmul2(p[1], hs);
        p[2] = __hmul2(p[2], hs); p[3] = __hmul2(p[3], hs);
        *(uint4*)&Qs[r * FSTR + 8 * fcl] = v;
    }

    float o[4][4];
#pragma unroll
    for (int j = 0; j < 4; j++)
#pragma unroll
        for (int c = 0; c < 4; c++) o[j][c] = 0.0f;
    float m0 = -1e30f, m1 = -1e30f, l0 = 0.0f, l1 = 0.0f;

    const unsigned qsb = sptr(Qs);
    const unsigned ksb = sptr(Ks);
    const unsigned vsb = sptr(Vs);
    const unsigned psb = sptr(Ps);

    for (int kt = 0; kt <= qt; kt++) {
        __syncthreads();
#pragma unroll
        for (int i = 0; i < 2; i++) {
            int r = frl + 32 * i;
            size_t grow = (size_t)(kt * 64 + r) * N_QKV + 8 * fcl;
            *(uint4*)&Ks[r * FSTR + 8 * fcl] = *(const uint4*)(kb + grow);
            *(uint4*)&Vs[r * FSTR + 8 * fcl] = *(const uint4*)(vb + grow);
        }
        __syncthreads();

        float s[4][4];
#pragma unroll
        for (int j = 0; j < 4; j++)
#pragma unroll
            for (int c = 0; c < 4; c++) s[j][c] = 0.0f;

#pragma unroll
        for (int kk = 0; kk < 4; kk++) {
            unsigned a0, a1, a2, a3;
            {
                int row = wm * 16 + lb * 8 + la;
                int ch  = 2 * kk + lc;
                ldsm4(a0, a1, a2, a3, qsb + (row * FSTR + ch * 8) * 2);
            }
#pragma unroll
            for (int ntp = 0; ntp < 2; ntp++) {
                unsigned b0, b1, b2, b3;
                int row = wn * 32 + ntp * 16 + lc * 8 + la;
                int ch  = 2 * kk + lb;
                ldsm4(b0, b1, b2, b3, ksb + (row * FSTR + ch * 8) * 2);
                mma16816(s[2 * ntp],     a0, a1, a2, a3, b0, b1);
                mma16816(s[2 * ntp + 1], a0, a1, a2, a3, b2, b3);
            }
        }

        if (kt == qt) {
#pragma unroll
            for (int j = 0; j < 4; j++) {
                int c = wn * 32 + j * 8 + 2 * q;
                if (c     > r0) s[j][0] = -1e30f;
                if (c + 1 > r0) s[j][1] = -1e30f;
                if (c     > r1) s[j][2] = -1e30f;
                if (c + 1 > r1) s[j][3] = -1e30f;
            }
        }

        float mx0 = -1e30f, mx1 = -1e30f;
#pragma unroll
        for (int j = 0; j < 4; j++) {
            mx0 = fmaxf(mx0, fmaxf(s[j][0], s[j][1]));
            mx1 = fmaxf(mx1, fmaxf(s[j][2], s[j][3]));
        }
        mx0 = fmaxf(mx0, __shfl_xor_sync(0xffffffffu, mx0, 1));
        mx0 = fmaxf(mx0, __shfl_xor_sync(0xffffffffu, mx0, 2));
        mx1 = fmaxf(mx1, __shfl_xor_sync(0xffffffffu, mx1, 1));
        mx1 = fmaxf(mx1, __shfl_xor_sync(0xffffffffu, mx1, 2));
        if (q == 0) {
            redmax[wn * 64 + r0] = mx0;
            redmax[wn * 64 + r1] = mx1;
        }
        __syncthreads();

        float mn0 = fmaxf(m0, fmaxf(redmax[r0], redmax[64 + r0]));
        float mn1 = fmaxf(m1, fmaxf(redmax[r1], redmax[64 + r1]));
        float cr0 = __expf(m0 - mn0);
        float cr1 = __expf(m1 - mn1);
        m0 = mn0; m1 = mn1;

        float sum0 = 0.0f, sum1 = 0.0f;
#pragma unroll
        for (int j = 0; j < 4; j++) {
            int c = wn * 32 + j * 8 + 2 * q;
            float p0 = __expf(s[j][0] - mn0);
            float p1 = __expf(s[j][1] - mn0);
            float p2 = __expf(s[j][2] - mn1);
            float p3 = __expf(s[j][3] - mn1);
            sum0 += p0 + p1;
            sum1 += p2 + p3;
            *(__half2*)&Ps[r0 * FSTR + c] = __floats2half2_rn(p0, p1);
            *(__half2*)&Ps[r1 * FSTR + c] = __floats2half2_rn(p2, p3);
        }
        sum0 += __shfl_xor_sync(0xffffffffu, sum0, 1);
        sum0 += __shfl_xor_sync(0xffffffffu, sum0, 2);
        sum1 += __shfl_xor_sync(0xffffffffu, sum1, 1);
        sum1 += __shfl_xor_sync(0xffffffffu, sum1, 2);
        if (q == 0) {
            redsum[wn * 64 + r0] = sum0;
            redsum[wn * 64 + r1] = sum1;
        }

#pragma unroll
        for (int j = 0; j < 4; j++) {
            o[j][0] *= cr0; o[j][1] *= cr0;
            o[j][2] *= cr1; o[j][3] *= cr1;
        }
        __syncthreads();

        l0 = l0 * cr0 + redsum[r0] + redsum[64 + r0];
        l1 = l1 * cr1 + redsum[r1] + redsum[64 + r1];

#pragma unroll
        for (int kkv = 0; kkv < 4; kkv++) {
            unsigned a0, a1, a2, a3;
            {
                int row = wm * 16 + lb * 8 + la;
                int ch  = 2 * kkv + lc;
                ldsm4(a0, a1, a2, a3, psb + (row * FSTR + ch * 8) * 2);
            }
#pragma unroll
            for (int ntp = 0; ntp < 2; ntp++) {
                unsigned b0, b1, b2, b3;
                int row = kkv * 16 + lb * 8 + la;
                int ch  = 4 * wn + 2 * ntp + lc;
                ldsm4t(b0, b1, b2, b3, vsb + (row * FSTR + ch * 8) * 2);
                mma16816(o[2 * ntp],     a0, a1, a2, a3, b0, b1);
                mma16816(o[2 * ntp + 1], a0, a1, a2, a3, b2, b3);
            }
        }
    }

    float il0 = 1.0f / l0;
    float il1 = 1.0f / l1;
    size_t row0 = (size_t)(b * T_ + qt * 64 + r0);
    size_t row1 = (size_t)(b * T_ + qt * 64 + r1);
#pragma unroll
    for (int j = 0; j < 4; j++) {
        int col = h * 64 + wn * 32 + j * 8 + 2 * q;
        *(__half2*)&out[row0 * C_ + col] = __floats2half2_rn(o[j][0] * il0, o[j][1] * il0);
        *(__half2*)&out[row1 * C_ + col] = __floats2half2_rn(o[j][2] * il1, o[j][3] * il1);
    }
}

// ---------------------------------------------------------------------------
// Host: tensormaps + launch
// ---------------------------------------------------------------------------
typedef CUresult (*PFN_encode)(CUtensorMap*, CUtensorMapDataType, cuuint32_t, void*,
                               const cuuint64_t*, const cuuint64_t*, const cuuint32_t*,
                               const cuuint32_t*, CUtensorMapInterleave, CUtensorMapSwizzle,
                               CUtensorMapL2promotion, CUtensorMapFloatOOBfill);

static void make_map(PFN_encode enc, CUtensorMap* tm, void* ptr,
                     unsigned long long cols, unsigned long long rows,
                     unsigned bx, unsigned by) {
    cuuint64_t dims[3]    = {cols, rows, 1};
    cuuint64_t strides[2] = {cols * 2, rows * cols * 2};
    cuuint32_t box[3]     = {bx, by, 1};
    cuuint32_t es[3]      = {1, 1, 1};
    enc(tm, CU_TENSOR_MAP_DATA_TYPE_FLOAT16, 3, ptr, dims, strides, box, es,
        CU_TENSOR_MAP_INTERLEAVE_NONE, CU_TENSOR_MAP_SWIZZLE_128B,
        CU_TENSOR_MAP_L2_PROMOTION_L2_128B, CU_TENSOR_MAP_FLOAT_OOB_FILL_NONE);
}

extern "C" void kernel_launch(void* const* d_in, const int* in_sizes, int n_in,
                              void* d_out, int out_size)
{
    const float* x      = (const float*)d_in[0];
    const float* W_qkv  = (const float*)d_in[1];
    const float* b_qkv  = (const float*)d_in[2];
    const float* W_proj = (const float*)d_in[3];
    const float* b_proj = (const float*)d_in[4];
    float* out = (float*)d_out;

    __half *hx, *hw1, *hw2, *qkv, *att;
    cudaGetSymbolAddress((void**)&hx,  g_hx);
    cudaGetSymbolAddress((void**)&hw1, g_hw1);
    cudaGetSymbolAddress((void**)&hw2, g_hw2);
    cudaGetSymbolAddress((void**)&qkv, g_qkv);
    cudaGetSymbolAddress((void**)&att, g_att);

    void* fnp = nullptr;
    cudaDriverEntryPointQueryResult qr;
    cudaGetDriverEntryPointByVersion("cuTensorMapEncodeTiled", &fnp, 12000,
                                     cudaEnableDefault, &qr);
    PFN_encode enc = (PFN_encode)fnp;

    CUtensorMap tmX, tmW1, tmAtt, tmW2;
    make_map(enc, &tmX,   hx,  C_, M_,    64, 128);
    make_map(enc, &tmW1,  hw1, C_, N_QKV, 64, 128);
    make_map(enc, &tmAtt, att, C_, M_,    64, 128);
    make_map(enc, &tmW2,  hw2, C_, C_,    64, 128);

    // 0) fp32 -> fp16 converts
    f2h_kernel<<<(M_ * C_ / 4 + 255) / 256, 256>>>(x, hx, M_ * C_ / 4);
    f2h_kernel<<<(N_QKV * C_ / 4 + 255) / 256, 256>>>(W_qkv, hw1, N_QKV * C_ / 4);
    f2h_kernel<<<(C_ * C_ / 4 + 255) / 256, 256>>>(W_proj, hw2, C_ * C_ / 4);

    // 1) qkv = x @ W_qkv^T + b_qkv (half out)
    cudaFuncSetAttribute((const void*)gemm_tma_kernel<true>,
                         cudaFuncAttributeMaxDynamicSharedMemorySize, GEMM_DSMEM);
    gemm_tma_kernel<true><<<dim3(N_QKV / 128, M_ / 128), 256, GEMM_DSMEM>>>(
        tmX, tmW1, b_qkv, qkv, N_QKV);

    // 2) flash attention (round-3 path)
    cudaFuncSetAttribute(flash_f16_kernel,
                         cudaFuncAttributeMaxDynamicSharedMemorySize, FL_SMEM_BYTES);
    flash_f16_kernel<<<dim3(T_ / 64, B_ * H_), 256, FL_SMEM_BYTES>>>(qkv, att);

    // 3) out = att @ W_proj^T + b_proj (float out)
    cudaFuncSetAttribute((const void*)gemm_tma_kernel<false>,
                         cudaFuncAttributeMaxDynamicSharedMemorySize, GEMM_DSMEM);
    gemm_tma_kernel<false><<<dim3(C_ / 128, M_ / 128), 256, GEMM_DSMEM>>>(
        tmAtt, tmW2, b_proj, out, C_);
}

// round 8
// speedup vs baseline: 6.8344x; 1.4323x over previous
#include <cuda_runtime.h>
#include <cuda.h>
#include <cuda_fp16.h>
#include <math.h>
#include <stdint.h>

// ---------------------------------------------------------------------------
// Problem constants
// ---------------------------------------------------------------------------
#define B_    4
#define T_    2048
#define C_    1024
#define H_    16
#define D_    64
#define M_    (B_ * T_)        // 8192
#define N_QKV (3 * C_)         // 3072

// Scratch (__device__ globals; allocation-free rule)
__device__ __half g_hx[M_ * C_];
__device__ __half g_hw1[N_QKV * C_];
__device__ __half g_hw2[C_ * C_];
__device__ __half g_qkv[(size_t)M_ * N_QKV];
__device__ __half g_att[M_ * C_];

// ---------------------------------------------------------------------------
// PTX helpers
// ---------------------------------------------------------------------------
__device__ __forceinline__ unsigned sptr(const void* p) {
    return (unsigned)__cvta_generic_to_shared(p);
}
__device__ __forceinline__ void ldsm4(unsigned& r0, unsigned& r1,
                                      unsigned& r2, unsigned& r3, unsigned a) {
    asm volatile("ldmatrix.sync.aligned.m8n8.x4.shared.b16 {%0,%1,%2,%3},[%4];"
                 : "=r"(r0), "=r"(r1), "=r"(r2), "=r"(r3) : "r"(a));
}
__device__ __forceinline__ void ldsm4t(unsigned& r0, unsigned& r1,
                                       unsigned& r2, unsigned& r3, unsigned a) {
    asm volatile("ldmatrix.sync.aligned.m8n8.x4.trans.shared.b16 {%0,%1,%2,%3},[%4];"
                 : "=r"(r0), "=r"(r1), "=r"(r2), "=r"(r3) : "r"(a));
}
__device__ __forceinline__ void mma16816(float* d,
                                         unsigned a0, unsigned a1, unsigned a2, unsigned a3,
                                         unsigned b0, unsigned b1) {
    asm volatile(
        "mma.sync.aligned.m16n8k16.row.col.f32.f16.f16.f32 "
        "{%0,%1,%2,%3},{%4,%5,%6,%7},{%8,%9},{%0,%1,%2,%3};"
        : "+f"(d[0]), "+f"(d[1]), "+f"(d[2]), "+f"(d[3])
        : "r"(a0), "r"(a1), "r"(a2), "r"(a3), "r"(b0), "r"(b1));
}
__device__ __forceinline__ void mbar_init(unsigned a, unsigned cnt) {
    asm volatile("mbarrier.init.shared.b64 [%0], %1;" :: "r"(a), "r"(cnt) : "memory");
}
__device__ __forceinline__ void mbar_expect(unsigned a, unsigned bytes) {
    asm volatile("mbarrier.arrive.expect_tx.shared.b64 _, [%0], %1;"
                 :: "r"(a), "r"(bytes) : "memory");
}
__device__ __forceinline__ void mbar_wait(unsigned a, unsigned parity) {
    asm volatile(
        "{\n\t.reg .pred P;\n\t"
        "W%=:\n\t"
        "mbarrier.try_wait.parity.acquire.cta.shared::cta.b64 P, [%0], %1, 0x989680;\n\t"
        "@P bra.uni D%=;\n\t"
        "bra.uni W%=;\n\t"
        "D%=:\n\t}"
        :: "r"(a), "r"(parity) : "memory");
}
__device__ __forceinline__ void tma3d(unsigned dst, const void* tm, int x, int y, unsigned mbar) {
    asm volatile(
        "cp.async.bulk.tensor.3d.shared::cta.global.tile.mbarrier::complete_tx::bytes "
        "[%0], [%1, {%2, %3, %4}], [%5];"
        :: "r"(dst), "l"(tm), "r"(x), "r"(y), "r"(0), "r"(mbar) : "memory");
}
__device__ __forceinline__ void fence_async_shared() {
    asm volatile("fence.proxy.async.shared::cta;" ::: "memory");
}

// ---------------------------------------------------------------------------
// fp32 -> fp16 convert
// ---------------------------------------------------------------------------
__global__ void f2h_kernel(const float* __restrict__ in, __half* __restrict__ out, int n4) {
    int i = blockIdx.x * blockDim.x + threadIdx.x;
    if (i < n4) {
        float4 v = ((const float4*)in)[i];
        __half2 h0 = __floats2half2_rn(v.x, v.y);
        __half2 h1 = __floats2half2_rn(v.z, v.w);
        uint2 u;
        u.x = *(unsigned*)&h0;
        u.y = *(unsigned*)&h1;
        ((uint2*)out)[i] = u;
    }
}

// ---------------------------------------------------------------------------
// TMA-fed HMMA GEMM (proven round 6) + 2 CTAs/SM via launch_bounds(256,2).
// ---------------------------------------------------------------------------
#define NSTAGE   3
#define ABYTES   (128 * 64 * 2)        // 16 KB per operand per stage
#define STAGEB   (2 * ABYTES)          // 32 KB
#define NKCHUNK  16                    // K=1024 / 64
#define GEMM_DSMEM (NSTAGE * STAGEB + 1024)

template <bool HALF_OUT>
__global__ __launch_bounds__(256, 2)
void gemm_tma_kernel(const __grid_constant__ CUtensorMap tmA,
                     const __grid_constant__ CUtensorMap tmW,
                     const float* __restrict__ bias,
                     void* __restrict__ Cc, int N)
{
    extern __shared__ char dsm_raw[];
    __shared__ __align__(8) unsigned long long s_mbar[NSTAGE];

    char* smb = (char*)(((uintptr_t)dsm_raw + 1023) & ~(uintptr_t)1023);
    const unsigned base = sptr(smb);

    const int tid  = threadIdx.x;
    const int warp = tid >> 5;
    const int lane = tid & 31;
    const int wm   = warp & 3;
    const int wn   = warp >> 2;
    const int g    = lane >> 2;
    const int q    = lane & 3;
    const int la   = lane & 7;
    const int lb   = (lane >> 3) & 1;
    const int lc   = lane >> 4;
    const int bm   = blockIdx.y * 128;
    const int bn   = blockIdx.x * 128;

    unsigned mf[NSTAGE];
#pragma unroll
    for (int s = 0; s < NSTAGE; s++) mf[s] = sptr(&s_mbar[s]);

    if (tid == 0)
#pragma unroll
        for (int s = 0; s < NSTAGE; s++) mbar_init(mf[s], 1);
    __syncthreads();

    if (tid == 0) {
#pragma unroll
        for (int s = 0; s < NSTAGE; s++) {
            mbar_expect(mf[s], STAGEB);
            tma3d(base + s * STAGEB,          &tmA, s * 64, bm, mf[s]);
            tma3d(base + s * STAGEB + ABYTES, &tmW, s * 64, bn, mf[s]);
        }
    }

    float acc[2][8][4];
#pragma unroll
    for (int mt = 0; mt < 2; mt++)
#pragma unroll
        for (int nt = 0; nt < 8; nt++)
#pragma unroll
            for (int c = 0; c < 4; c++) acc[mt][nt][c] = 0.0f;

    for (int c = 0; c < NKCHUNK; c++) {
        const int s = c % NSTAGE;
        const unsigned ph = (unsigned)((c / NSTAGE) & 1);
        mbar_wait(mf[s], ph);

        const unsigned abase = base + s * STAGEB;
        const unsigned bbase = abase + ABYTES;

#pragma unroll
        for (int kk = 0; kk < 4; kk++) {
            unsigned a[2][4];
#pragma unroll
            for (int mt = 0; mt < 2; mt++) {
                int row = wm * 32 + mt * 16 + lb * 8 + la;
                int ch  = (2 * kk + lc) ^ (row & 7);
                ldsm4(a[mt][0], a[mt][1], a[mt][2], a[mt][3],
                      abase + row * 128 + ch * 16);
            }
            unsigned bfr[4][4];
#pragma unroll
            for (int ntp = 0; ntp < 4; ntp++) {
                int row = wn * 64 + ntp * 16 + lc * 8 + la;
                int ch  = (2 * kk + lb) ^ (row & 7);
                ldsm4(bfr[ntp][0], bfr[ntp][1], bfr[ntp][2], bfr[ntp][3],
                      bbase + row * 128 + ch * 16);
            }
#pragma unroll
            for (int mt = 0; mt < 2; mt++)
#pragma unroll
                for (int ntp = 0; ntp < 4; ntp++) {
                    mma16816(acc[mt][2 * ntp],     a[mt][0], a[mt][1], a[mt][2], a[mt][3],
                             bfr[ntp][0], bfr[ntp][1]);
                    mma16816(acc[mt][2 * ntp + 1], a[mt][0], a[mt][1], a[mt][2], a[mt][3],
                             bfr[ntp][2], bfr[ntp][3]);
                }
        }

        __syncthreads();   // all reads of stage s complete

        if (tid == 0) {
            const int cn = c + NSTAGE;
            if (cn < NKCHUNK) {
                fence_async_shared();
                mbar_expect(mf[s], STAGEB);
                tma3d(abase, &tmA, cn * 64, bm, mf[s]);
                tma3d(bbase, &tmW, cn * 64, bn, mf[s]);
            }
        }
    }

    float2 bv[8];
#pragma unroll
    for (int nt = 0; nt < 8; nt++) {
        int col = bn + wn * 64 + nt * 8 + 2 * q;
        bv[nt].x = bias[col];
        bv[nt].y = bias[col + 1];
    }
#pragma unroll
    for (int mt = 0; mt < 2; mt++) {
        int row = bm + wm * 32 + mt * 16 + g;
#pragma unroll
        for (int nt = 0; nt < 8; nt++) {
            int col = bn + wn * 64 + nt * 8 + 2 * q;
            float x0 = acc[mt][nt][0] + bv[nt].x;
            float y0 = acc[mt][nt][1] + bv[nt].y;
            float x1 = acc[mt][nt][2] + bv[nt].x;
            float y1 = acc[mt][nt][3] + bv[nt].y;
            if (HALF_OUT) {
                __half* O = (__half*)Cc;
                *(__half2*)&O[(size_t)row * N + col]       = __floats2half2_rn(x0, y0);
                *(__half2*)&O[(size_t)(row + 8) * N + col] = __floats2half2_rn(x1, y1);
            } else {
                float* O = (float*)Cc;
                *(float2*)&O[(size_t)row * N + col]       = make_float2(x0, y0);
                *(float2*)&O[(size_t)(row + 8) * N + col] = make_float2(x1, y1);
            }
        }
    }
}

// ---------------------------------------------------------------------------
// Flash attention: fp16 mma, double-buffered TMA K/V (SW128).
// FIX: dyn smem base aligned to 1024 and K/V buffers placed FIRST so every
// buffer start is a multiple of 1024 (TMA swizzle atom). Layout:
//   base: K0(8K) K1(8K) V0(8K) V1(8K) | Qs[64*72] | Ps[64*72]
// ---------------------------------------------------------------------------
#define FSTR 72
#define FL_TILEB  (64 * 64 * 2)                     // 8 KB
#define FL_DSMEM  (4 * FL_TILEB + 2 * 64 * FSTR * 2 + 1024)

__global__ __launch_bounds__(256, 2)
void flash_f16_kernel(const __grid_constant__ CUtensorMap tmKV,
                      const __half* __restrict__ qkv, __half* __restrict__ out)
{
    extern __shared__ char fraw[];
    __shared__ float redmax[128];
    __shared__ float redsum[128];
    __shared__ __align__(8) unsigned long long s_fm[2];

    char* fb = (char*)(((uintptr_t)fraw + 1023) & ~(uintptr_t)1023);
    const unsigned base = sptr(fb);
    const unsigned kb0 = base;                      // 1024-aligned
    const unsigned kb1 = kb0 + FL_TILEB;            // +8192
    const unsigned vb0 = kb1 + FL_TILEB;            // +16384
    const unsigned vb1 = vb0 + FL_TILEB;            // +24576
    __half* Qs = (__half*)(fb + 4 * FL_TILEB);
    __half* Ps = Qs + 64 * FSTR;
    const unsigned qsb = sptr(Qs);
    const unsigned psb = sptr(Ps);
    const unsigned kbuf[2] = {kb0, kb1};
    const unsigned vbuf[2] = {vb0, vb1};
    const unsigned fm[2]   = {sptr(&s_fm[0]), sptr(&s_fm[1])};

    const int qt   = (int)gridDim.x - 1 - (int)blockIdx.x;  // heavy tiles first
    const int bh   = blockIdx.y;
    const int bb   = bh >> 4;
    const int h    = bh & 15;
    const int tid  = threadIdx.x;
    const int warp = tid >> 5;
    const int lane = tid & 31;
    const int wm   = warp >> 1;
    const int wn   = warp & 1;
    const int g    = lane >> 2;
    const int q    = lane & 3;
    const int la   = lane & 7;
    const int lb   = (lane >> 3) & 1;
    const int lc   = lane >> 4;
    const int r0   = wm * 16 + g;
    const int r1   = r0 + 8;

    if (tid == 0) {
        mbar_init(fm[0], 1);
        mbar_init(fm[1], 1);
    }

    // Load Q tile (scaled by 1/8, exact in fp16), padded layout
    const __half* qb = qkv + (size_t)(bb * T_) * N_QKV + h * D_;
    const int frl = (tid & 7) + 8 * (tid >> 6);
    const int fcl = (tid >> 3) & 7;
    const __half2 hs = __floats2half2_rn(0.125f, 0.125f);
#pragma unroll
    for (int i = 0; i < 2; i++) {
        int r = frl + 32 * i;
        uint4 v = *(const uint4*)(qb + (size_t)(qt * 64 + r) * N_QKV + 8 * fcl);
        __half2* p = (__half2*)&v;
        p[0] = __hmul2(p[0], hs); p[1] = __hmul2(p[1], hs);
        p[2] = __hmul2(p[2], hs); p[3] = __hmul2(p[3], hs);
        *(uint4*)&Qs[r * FSTR + 8 * fcl] = v;
    }
    __syncthreads();   // mbar init + Q stores visible

    if (tid == 0) {
        mbar_expect(fm[0], 2 * FL_TILEB);
        tma3d(kbuf[0], &tmKV, C_ + h * 64,     bb * T_, fm[0]);
        tma3d(vbuf[0], &tmKV, 2 * C_ + h * 64, bb * T_, fm[0]);
    }

    float o[4][4];
#pragma unroll
    for (int j = 0; j < 4; j++)
#pragma unroll
        for (int c = 0; c < 4; c++) o[j][c] = 0.0f;
    float m0 = -1e30f, m1 = -1e30f, l0 = 0.0f, l1 = 0.0f;

    for (int kt = 0; kt <= qt; kt++) {
        const int buf = kt & 1;
        mbar_wait(fm[buf], (unsigned)((kt >> 1) & 1));

        // S = Q K^T  (Q padded; K SW128-swizzled)
        float s[4][4];
#pragma unroll
        for (int j = 0; j < 4; j++)
#pragma unroll
            for (int c = 0; c < 4; c++) s[j][c] = 0.0f;

#pragma unroll
        for (int kk = 0; kk < 4; kk++) {
            unsigned a0, a1, a2, a3;
            {
                int row = wm * 16 + lb * 8 + la;
                int ch  = 2 * kk + lc;
                ldsm4(a0, a1, a2, a3, qsb + (row * FSTR + ch * 8) * 2);
            }
#pragma unroll
            for (int ntp = 0; ntp < 2; ntp++) {
                unsigned b0, b1, b2, b3;
                int row = wn * 32 + ntp * 16 + lc * 8 + la;
                int ch  = (2 * kk + lb) ^ (row & 7);
                ldsm4(b0, b1, b2, b3, kbuf[buf] + row * 128 + ch * 16);
                mma16816(s[2 * ntp],     a0, a1, a2, a3, b0, b1);
                mma16816(s[2 * ntp + 1], a0, a1, a2, a3, b2, b3);
            }
        }

        if (kt == qt) {
#pragma unroll
            for (int j = 0; j < 4; j++) {
                int c = wn * 32 + j * 8 + 2 * q;
                if (c     > r0) s[j][0] = -1e30f;
                if (c + 1 > r0) s[j][1] = -1e30f;
                if (c     > r1) s[j][2] = -1e30f;
                if (c + 1 > r1) s[j][3] = -1e30f;
            }
        }

        float mx0 = -1e30f, mx1 = -1e30f;
#pragma unroll
        for (int j = 0; j < 4; j++) {
            mx0 = fmaxf(mx0, fmaxf(s[j][0], s[j][1]));
            mx1 = fmaxf(mx1, fmaxf(s[j][2], s[j][3]));
        }
        mx0 = fmaxf(mx0, __shfl_xor_sync(0xffffffffu, mx0, 1));
        mx0 = fmaxf(mx0, __shfl_xor_sync(0xffffffffu, mx0, 2));
        mx1 = fmaxf(mx1, __shfl_xor_sync(0xffffffffu, mx1, 1));
        mx1 = fmaxf(mx1, __shfl_xor_sync(0xffffffffu, mx1, 2));
        if (q == 0) {
            redmax[wn * 64 + r0] = mx0;
            redmax[wn * 64 + r1] = mx1;
        }
        __syncthreads();   // first block-wide sync of iter kt: all of iter kt-1 done

        // Prefetch kt+1 into the other buffer (last read in iteration kt-1).
        if (tid == 0 && kt < qt) {
            fence_async_shared();
            const int nb = buf ^ 1;
            mbar_expect(fm[nb], 2 * FL_TILEB);
            tma3d(kbuf[nb], &tmKV, C_ + h * 64,     bb * T_ + (kt + 1) * 64, fm[nb]);
            tma3d(vbuf[nb], &tmKV, 2 * C_ + h * 64, bb * T_ + (kt + 1) * 64, fm[nb]);
        }

        float mn0 = fmaxf(m0, fmaxf(redmax[r0], redmax[64 + r0]));
        float mn1 = fmaxf(m1, fmaxf(redmax[r1], redmax[64 + r1]));
        float cr0 = __expf(m0 - mn0);
        float cr1 = __expf(m1 - mn1);
        m0 = mn0; m1 = mn1;

        float sum0 = 0.0f, sum1 = 0.0f;
#pragma unroll
        for (int j = 0; j < 4; j++) {
            int c = wn * 32 + j * 8 + 2 * q;
            float p0 = __expf(s[j][0] - mn0);
            float p1 = __expf(s[j][1] - mn0);
            float p2 = __expf(s[j][2] - mn1);
            float p3 = __expf(s[j][3] - mn1);
            sum0 += p0 + p1;
            sum1 += p2 + p3;
            *(__half2*)&Ps[r0 * FSTR + c] = __floats2half2_rn(p0, p1);
            *(__half2*)&Ps[r1 * FSTR + c] = __floats2half2_rn(p2, p3);
        }
        sum0 += __shfl_xor_sync(0xffffffffu, sum0, 1);
        sum0 += __shfl_xor_sync(0xffffffffu, sum0, 2);
        sum1 += __shfl_xor_sync(0xffffffffu, sum1, 1);
        sum1 += __shfl_xor_sync(0xffffffffu, sum1, 2);
        if (q == 0) {
            redsum[wn * 64 + r0] = sum0;
            redsum[wn * 64 + r1] = sum1;
        }

#pragma unroll
        for (int j = 0; j < 4; j++) {
            o[j][0] *= cr0; o[j][1] *= cr0;
            o[j][2] *= cr1; o[j][3] *= cr1;
        }
        __syncthreads();   // Ps writes + redsum visible

        l0 = l0 * cr0 + redsum[r0] + redsum[64 + r0];
        l1 = l1 * cr1 + redsum[r1] + redsum[64 + r1];

        // O += P V   (P padded; V SW128-swizzled, transposed ldmatrix)
#pragma unroll
        for (int kkv = 0; kkv < 4; kkv++) {
            unsigned a0, a1, a2, a3;
            {
                int row = wm * 16 + lb * 8 + la;
                int ch  = 2 * kkv + lc;
                ldsm4(a0, a1, a2, a3, psb + (row * FSTR + ch * 8) * 2);
            }
#pragma unroll
            for (int ntp = 0; ntp < 2; ntp++) {
                unsigned b0, b1, b2, b3;
                int row = kkv * 16 + lb * 8 + la;
                int ch  = (4 * wn + 2 * ntp + lc) ^ (row & 7);
                ldsm4t(b0, b1, b2, b3, vbuf[buf] + row * 128 + ch * 16);
                mma16816(o[2 * ntp],     a0, a1, a2, a3, b0, b1);
                mma16816(o[2 * ntp + 1], a0, a1, a2, a3, b2, b3);
            }
        }
    }

    float il0 = 1.0f / l0;
    float il1 = 1.0f / l1;
    size_t row0 = (size_t)(bb * T_ + qt * 64 + r0);
    size_t row1 = (size_t)(bb * T_ + qt * 64 + r1);
#pragma unroll
    for (int j = 0; j < 4; j++) {
        int col = h * 64 + wn * 32 + j * 8 + 2 * q;
        *(__half2*)&out[row0 * C_ + col] = __floats2half2_rn(o[j][0] * il0, o[j][1] * il0);
        *(__half2*)&out[row1 * C_ + col] = __floats2half2_rn(o[j][2] * il1, o[j][3] * il1);
    }
}

// ---------------------------------------------------------------------------
// Host: tensormaps + launch
// ---------------------------------------------------------------------------
typedef CUresult (*PFN_encode)(CUtensorMap*, CUtensorMapDataType, cuuint32_t, void*,
                               const cuuint64_t*, const cuuint64_t*, const cuuint32_t*,
                               const cuuint32_t*, CUtensorMapInterleave, CUtensorMapSwizzle,
                               CUtensorMapL2promotion, CUtensorMapFloatOOBfill);

static void make_map(PFN_encode enc, CUtensorMap* tm, void* ptr,
                     unsigned long long cols, unsigned long long rows,
                     unsigned bx, unsigned by) {
    cuuint64_t dims[3]    = {cols, rows, 1};
    cuuint64_t strides[2] = {cols * 2, rows * cols * 2};
    cuuint32_t box[3]     = {bx, by, 1};
    cuuint32_t es[3]      = {1, 1, 1};
    enc(tm, CU_TENSOR_MAP_DATA_TYPE_FLOAT16, 3, ptr, dims, strides, box, es,
        CU_TENSOR_MAP_INTERLEAVE_NONE, CU_TENSOR_MAP_SWIZZLE_128B,
        CU_TENSOR_MAP_L2_PROMOTION_L2_128B, CU_TENSOR_MAP_FLOAT_OOB_FILL_NONE);
}

extern "C" void kernel_launch(void* const* d_in, const int* in_sizes, int n_in,
                              void* d_out, int out_size)
{
    const float* x      = (const float*)d_in[0];
    const float* W_qkv  = (const float*)d_in[1];
    const float* b_qkv  = (const float*)d_in[2];
    const float* W_proj = (const float*)d_in[3];
    const float* b_proj = (const float*)d_in[4];
    float* out = (float*)d_out;

    __half *hx, *hw1, *hw2, *qkv, *att;
    cudaGetSymbolAddress((void**)&hx,  g_hx);
    cudaGetSymbolAddress((void**)&hw1, g_hw1);
    cudaGetSymbolAddress((void**)&hw2, g_hw2);
    cudaGetSymbolAddress((void**)&qkv, g_qkv);
    cudaGetSymbolAddress((void**)&att, g_att);

    void* fnp = nullptr;
    cudaDriverEntryPointQueryResult qr;
    cudaGetDriverEntryPointByVersion("cuTensorMapEncodeTiled", &fnp, 12000,
                                     cudaEnableDefault, &qr);
    PFN_encode enc = (PFN_encode)fnp;

    CUtensorMap tmX, tmW1, tmAtt, tmW2, tmKV;
    make_map(enc, &tmX,   hx,  C_,    M_,    64, 128);
    make_map(enc, &tmW1,  hw1, C_,    N_QKV, 64, 128);
    make_map(enc, &tmAtt, att, C_,    M_,    64, 128);
    make_map(enc, &tmW2,  hw2, C_,    C_,    64, 128);
    make_map(enc, &tmKV,  qkv, N_QKV, M_,    64, 64);

    // 0) fp32 -> fp16 converts
    f2h_kernel<<<(M_ * C_ / 4 + 255) / 256, 256>>>(x, hx, M_ * C_ / 4);
    f2h_kernel<<<(N_QKV * C_ / 4 + 255) / 256, 256>>>(W_qkv, hw1, N_QKV * C_ / 4);
    f2h_kernel<<<(C_ * C_ / 4 + 255) / 256, 256>>>(W_proj, hw2, C_ * C_ / 4);

    // 1) qkv = x @ W_qkv^T + b_qkv (half out)
    cudaFuncSetAttribute((const void*)gemm_tma_kernel<true>,
                         cudaFuncAttributeMaxDynamicSharedMemorySize, GEMM_DSMEM);
    gemm_tma_kernel<true><<<dim3(N_QKV / 128, M_ / 128), 256, GEMM_DSMEM>>>(
        tmX, tmW1, b_qkv, qkv, N_QKV);

    // 2) flash attention (double-buffered TMA K/V, 1024-aligned buffers)
    cudaFuncSetAttribute(flash_f16_kernel,
                         cudaFuncAttributeMaxDynamicSharedMemorySize, FL_DSMEM);
    flash_f16_kernel<<<dim3(T_ / 64, B_ * H_), 256, FL_DSMEM>>>(tmKV, qkv, att);

    // 3) out = att @ W_proj^T + b_proj (float out)
    cudaFuncSetAttribute((const void*)gemm_tma_kernel<false>,
                         cudaFuncAttributeMaxDynamicSharedMemorySize, GEMM_DSMEM);
    gemm_tma_kernel<false><<<dim3(C_ / 128, M_ / 128), 256, GEMM_DSMEM>>>(
        tmAtt, tmW2, b_proj, out, C_);
}